// round 8
// baseline (speedup 1.0000x reference)
#include <cuda_runtime.h>
#include <cuda_fp16.h>
#include <math.h>

#define N_NODES 8192
#define N_EDGES 32768
#define FN 32
#define FE 16
#define H 73
#define HH (H*H)            // 5329
#define KP 80               // padded K (5 x k16)
#define SEG 80              // per-channel segment width (74 real + 6 zero)
#define TW2 5920            // W2e width: 73*80, = 37*160
#define AHW 160             // concat row: [agg16 (80) | h16 (80)]
#define GGW 512
#define NB 64
#define T_MP 3
#define T_S2S 12

#define SRCB 64             // source nodes per k_step block
#define ASP 88
#define BSP 168
#define CSP 170

// ---------------- device scratch ----------------
__device__ float g_h[N_NODES * H];
__device__ __half g_ah[N_NODES * AHW];
__device__ __half g_RHe[N_EDGES * SEG];
__device__ __half g_RHs[N_EDGES * SEG];           // sorted by src
__device__ float g_agg[N_NODES * H];
__device__ __half g_W2e[KP * TW2];
__device__ __half g_Wgru[AHW * GGW];
__device__ float g_GG[N_NODES * GGW];
__device__ int g_off[N_NODES + 1];
__device__ int g_cur[N_NODES];
__device__ int g_eord[N_EDGES];
__device__ int g_srcS[N_EDGES];
__device__ int g_tgtS[N_EDGES];

__device__ __forceinline__ float sigf(float x) { return 1.0f / (1.0f + expf(-x)); }

__device__ __forceinline__ void ldsm_x4(unsigned &r0, unsigned &r1, unsigned &r2, unsigned &r3, unsigned addr) {
    asm volatile("ldmatrix.sync.aligned.m8n8.x4.shared.b16 {%0,%1,%2,%3},[%4];"
                 : "=r"(r0), "=r"(r1), "=r"(r2), "=r"(r3) : "r"(addr));
}
__device__ __forceinline__ void ldsm_x4t(unsigned &r0, unsigned &r1, unsigned &r2, unsigned &r3, unsigned addr) {
    asm volatile("ldmatrix.sync.aligned.m8n8.x4.trans.shared.b16 {%0,%1,%2,%3},[%4];"
                 : "=r"(r0), "=r"(r1), "=r"(r2), "=r"(r3) : "r"(addr));
}
__device__ __forceinline__ void mma16816(float* d, const unsigned* a, unsigned b0, unsigned b1) {
    asm volatile("mma.sync.aligned.m16n8k16.row.col.f32.f16.f16.f32 "
                 "{%0,%1,%2,%3},{%4,%5,%6,%7},{%8,%9},{%0,%1,%2,%3};"
                 : "+f"(d[0]), "+f"(d[1]), "+f"(d[2]), "+f"(d[3])
                 : "r"(a[0]), "r"(a[1]), "r"(a[2]), "r"(a[3]), "r"(b0), "r"(b1));
}
__device__ __forceinline__ void cpa16(unsigned s, const void* g) {
    asm volatile("cp.async.cg.shared.global [%0], [%1], 16;" :: "r"(s), "l"(g));
}

// ---------------- prepW2 ----------------
__global__ __launch_bounds__(256) void k_prepW2(const float* __restrict__ W2,
                                                const float* __restrict__ b2) {
    __shared__ float tile[74 * 73];
    int i = blockIdx.x;
    int tid = threadIdx.x;
    for (int idx = tid; idx < 74 * 73; idx += 256) {
        int kk = idx / 73, j = idx % 73;
        tile[idx] = (kk < H) ? W2[(size_t)kk * HH + i * H + j] : b2[i * H + j];
    }
    __syncthreads();
    for (int idx = tid; idx < 73 * SEG; idx += 256) {
        int j = idx / SEG, kk = idx % SEG;
        float v = (kk < 74) ? tile[kk * 73 + j] : 0.0f;
        g_W2e[(size_t)j * TW2 + i * SEG + kk] = __float2half(v);
    }
    const int PAD1 = 7 * TW2, PADT = PAD1 + 73 * 80;
    for (int p = blockIdx.x * 256 + tid; p < PADT; p += 73 * 256) {
        int j, c;
        if (p < PAD1) { j = 73 + p / TW2; c = p % TW2; }
        else { int q = p - PAD1; j = q / 80; c = 5840 + q % 80; }
        g_W2e[(size_t)j * TW2 + c] = __float2half(0.0f);
    }
}

// ---------------- prep: h0 + RH fp16 ----------------
#define NB_H0 ((N_NODES * KP) / 256)      // 2560
#define NB_RH ((N_EDGES * SEG) / 256)     // 10240
__global__ void k_prep(const float* __restrict__ nf, const float* __restrict__ Win,
                       const float* __restrict__ bin, const float* __restrict__ ef,
                       const float* __restrict__ W1, const float* __restrict__ b1) {
    int b = blockIdx.x;
    int tid = threadIdx.x;
    if (b < NB_H0) {
        int idx = b * 256 + tid;
        if (idx < N_NODES * H) g_agg[idx] = 0.0f;
        int n = idx / KP, c = idx % KP;
        if (c >= H) { g_ah[n * AHW + KP + c] = __float2half(0.0f); return; }
        const float* x = nf + n * FN;
        float acc = bin[c];
#pragma unroll
        for (int k = 0; k < FN; k++) acc += x[k] * Win[k * H + c];
        g_h[n * H + c] = acc;
        g_ah[n * AHW + KP + c] = __float2half(acc);
    } else {
        int idx = (b - NB_H0) * 256 + tid;
        int e = idx / SEG, c = idx % SEG;
        float v;
        if (c < H) {
            const float* x = ef + e * FE;
            float acc = b1[c];
#pragma unroll
            for (int k = 0; k < FE; k++) acc += x[k] * W1[k * H + c];
            v = fmaxf(acc, 0.0f);
        } else v = (c == H) ? 1.0f : 0.0f;
        g_RHe[idx] = __float2half(v);
    }
}

// ---------------- scan with in-kernel histogram ----------------
__global__ __launch_bounds__(1024) void k_scan(const int* __restrict__ Esrc) {
    __shared__ int hist[N_NODES];
    __shared__ int sm_[1024];
    int tid = threadIdx.x;
    for (int i = tid; i < N_NODES; i += 1024) hist[i] = 0;
    __syncthreads();
    for (int e = tid; e < N_EDGES; e += 1024) atomicAdd(&hist[Esrc[e]], 1);
    __syncthreads();
    int base = tid * 8;
    int v[8], s = 0;
#pragma unroll
    for (int i = 0; i < 8; i++) { v[i] = hist[base + i]; s += v[i]; }
    sm_[tid] = s;
    __syncthreads();
    for (int off = 1; off < 1024; off <<= 1) {
        int t = (tid >= off) ? sm_[tid - off] : 0;
        __syncthreads();
        sm_[tid] += t;
        __syncthreads();
    }
    int run = sm_[tid] - s;
#pragma unroll
    for (int i = 0; i < 8; i++) {
        g_off[base + i] = run;
        g_cur[base + i] = run;
        run += v[i];
    }
    if (tid == 1023) g_off[N_NODES] = run;
}

// ---------------- misc: scatter edges + block-diag GRU weight ----------------
__global__ void k_misc(const int* __restrict__ Esrc, const int* __restrict__ Etgt,
                       const float* __restrict__ Wih, const float* __restrict__ Whh) {
    int idx = blockIdx.x * blockDim.x + threadIdx.x;
    if (idx < N_EDGES) {
        int src = Esrc[idx];
        int p = atomicAdd(&g_cur[src], 1);
        g_eord[p] = idx;
        g_srcS[p] = src;
        g_tgtS[p] = Etgt[idx];
    }
    if (idx < AHW * GGW) {
        int k = idx >> 9, c = idx & (GGW - 1);
        float v = 0.0f;
        if (k < H && c < 3 * H) v = Wih[(size_t)c * H + k];
        else if (k >= KP && k < KP + H && c >= 224 && c < 224 + 3 * H)
            v = Whh[(size_t)(c - 224) * H + (k - KP)];
        g_Wgru[idx] = __float2half(v);
    }
}

// ---------------- sort RH rows by src (uint granularity) ----------------
__global__ void k_sortRH() {
    int idx = blockIdx.x * blockDim.x + threadIdx.x;
    if (idx >= N_EDGES * 40) return;
    int p = idx / 40, q = idx - p * 40;
    reinterpret_cast<unsigned*>(g_RHs)[idx] =
        reinterpret_cast<const unsigned*>(g_RHe)[(size_t)g_eord[p] * 40 + q];
}

// ---------------- fused step kernel: T2 tile GEMM + message epilogue -------------
// Block owns SRCB=64 src nodes; loops over 37 column tiles (2 channels each).
// smem (halfs): As[64][88] @0, Bs[2][80][168] @5632, Cs[64][170] @32512.
__global__ __launch_bounds__(256) void k_step(const __half* __restrict__ A) {
    extern __shared__ __half sh[];
    __half* As = sh;
    __half* Bs0 = sh + 5632;
    __half* Bs1 = sh + 5632 + 80 * BSP;
    __half* Cs = sh + 32512;

    int tid = threadIdx.x;
    int m0 = blockIdx.x * SRCB;
    int p0 = g_off[m0], p1 = g_off[m0 + SRCB];
    if (p0 == p1) return;

    // A strip (64 x 80) -> smem, once
    for (int idx = tid; idx < SRCB * 10; idx += 256) {
        int r = idx / 10, c = idx - r * 10;
        *reinterpret_cast<uint4*>(&As[r * ASP + c * 8]) =
            *reinterpret_cast<const uint4*>(A + (size_t)(m0 + r) * AHW + c * 8);
    }

    // prefetch tile 0 into Bs0
    {
        unsigned bb = (unsigned)__cvta_generic_to_shared(Bs0);
        for (int idx = tid; idx < 1600; idx += 256) {
            int k = idx / 20, c = idx - k * 20;
            cpa16(bb + (unsigned)((k * BSP + c * 8) * 2),
                  g_W2e + (size_t)k * TW2 + c * 8);
        }
        asm volatile("cp.async.commit_group;" ::: "memory");
    }
    __syncthreads();

    int wid = tid >> 5, lane = tid & 31;
    int wm0 = (wid & 3) * 16;
    int wn0 = (wid >> 2) * 80;
    int lr = lane & 15, lc = (lane >> 4) * 8;
    int gr = lane >> 2, gc = (lane & 3) * 2;

    // A fragments hoisted: constant across all 37 tiles
    unsigned a_base = (unsigned)__cvta_generic_to_shared(As);
    unsigned af[5][4];
#pragma unroll
    for (int ks = 0; ks < 5; ks++) {
        unsigned addr = a_base + (unsigned)(((wm0 + lr) * ASP + ks * 16 + lc) * 2);
        ldsm_x4(af[ks][0], af[ks][1], af[ks][2], af[ks][3], addr);
    }

    unsigned bbase[2] = {(unsigned)__cvta_generic_to_shared(Bs0),
                         (unsigned)__cvta_generic_to_shared(Bs1)};
    __half* bptr[2] = {Bs0, Bs1};

    for (int ti = 0; ti < 37; ti++) {
        int cur = ti & 1, nxt = cur ^ 1;
        asm volatile("cp.async.wait_group 0;" ::: "memory");
        __syncthreads();

        // prefetch next tile into the other buffer
        if (ti + 1 < 37) {
            unsigned bb = bbase[nxt];
            const __half* gsrc = g_W2e + (ti + 1) * 160;
            for (int idx = tid; idx < 1600; idx += 256) {
                int k = idx / 20, c = idx - k * 20;
                cpa16(bb + (unsigned)((k * BSP + c * 8) * 2),
                      gsrc + (size_t)k * TW2 + c * 8);
            }
        }
        asm volatile("cp.async.commit_group;" ::: "memory");

        // MMA on current tile
        float acc[10][4];
#pragma unroll
        for (int j = 0; j < 10; j++)
#pragma unroll
            for (int q = 0; q < 4; q++) acc[j][q] = 0.0f;

        unsigned b_base = bbase[cur];
#pragma unroll
        for (int ks = 0; ks < 5; ks++) {
            int k0 = ks * 16;
            unsigned bf[5][4];
#pragma unroll
            for (int nj = 0; nj < 5; nj++) {
                unsigned addr = b_base + (unsigned)(((k0 + lr) * BSP + wn0 + nj * 16 + lc) * 2);
                ldsm_x4t(bf[nj][0], bf[nj][1], bf[nj][2], bf[nj][3], addr);
            }
#pragma unroll
            for (int nj = 0; nj < 5; nj++) {
                mma16816(acc[2 * nj], af[ks], bf[nj][0], bf[nj][1]);
                mma16816(acc[2 * nj + 1], af[ks], bf[nj][2], bf[nj][3]);
            }
        }
        (void)bptr;

        // stage C tile (64 x 160) in smem as fp16
#pragma unroll
        for (int f = 0; f < 10; f++) {
            int col = wn0 + f * 8 + gc;
#pragma unroll
            for (int rr = 0; rr < 2; rr++) {
                int row = wm0 + gr + rr * 8;
                *reinterpret_cast<__half2*>(&Cs[row * CSP + col]) =
                    __floats2half2_rn(acc[f][rr * 2], acc[f][rr * 2 + 1]);
            }
        }
        __syncthreads();

        // message epilogue for channels ch0=2*ti, ch1=2*ti+1
        int ch0 = 2 * ti, ch1 = 2 * ti + 1;
        for (int p = p0 + tid; p < p1; p += 256) {
            int row = g_srcS[p] - m0;
            const __half2* rh = reinterpret_cast<const __half2*>(g_RHs + (size_t)p * SEG);
            const __half2* c0 = reinterpret_cast<const __half2*>(&Cs[row * CSP]);
            const __half2* c1 = reinterpret_cast<const __half2*>(&Cs[row * CSP + 80]);
            float a0 = 0.0f, a1 = 0.0f;
#pragma unroll
            for (int q = 0; q < 37; q++) {
                float2 r = __half22float2(rh[q]);
                float2 v0 = __half22float2(c0[q]);
                float2 v1 = __half22float2(c1[q]);
                a0 += r.x * v0.x + r.y * v0.y;
                a1 += r.x * v1.x + r.y * v1.y;
            }
            int tgt = g_tgtS[p];
            atomicAdd(&g_agg[(size_t)tgt * H + ch0], a0);
            if (ch1 < H) atomicAdd(&g_agg[(size_t)tgt * H + ch1], a1);
        }
        __syncthreads();
    }
}

// ---------------- gates GEMM: GG[M,448] = ah[M,160] @ Wgru[160,512] ----------------
template <int KT>
__global__ __launch_bounds__(256) void k_hgemm(const __half* __restrict__ A, int lda,
                                               const __half* __restrict__ B, int ldb,
                                               float* __restrict__ C, int ldc, int nreal) {
    const int AP = KT * 16 + 8;
    extern __shared__ __half smh[];
    __half* As = smh;
    __half* Bs = smh + 128 * AP;
    int tid = threadIdx.x;
    int m0 = blockIdx.y * 128;
    int n0 = blockIdx.x * 128;

    for (int idx = tid; idx < 128 * 2 * KT; idx += 256) {
        int r = idx / (2 * KT), c = idx % (2 * KT);
        *reinterpret_cast<uint4*>(&As[r * AP + c * 8]) =
            *reinterpret_cast<const uint4*>(A + (size_t)(m0 + r) * lda + c * 8);
    }
    for (int idx = tid; idx < KT * 256; idx += 256) {
        int k = idx >> 4, c = idx & 15;
        *reinterpret_cast<uint4*>(&Bs[k * 136 + c * 8]) =
            *reinterpret_cast<const uint4*>(B + (size_t)k * ldb + n0 + c * 8);
    }
    __syncthreads();

    int wid = tid >> 5, lane = tid & 31;
    int wm0 = (wid & 3) * 32;
    int wn0 = (wid >> 2) * 64;

    float acc[2][8][4];
#pragma unroll
    for (int i = 0; i < 2; i++)
#pragma unroll
        for (int j = 0; j < 8; j++)
#pragma unroll
            for (int q = 0; q < 4; q++) acc[i][j][q] = 0.0f;

    unsigned a_base = (unsigned)__cvta_generic_to_shared(As);
    unsigned b_base = (unsigned)__cvta_generic_to_shared(Bs);
    int lr = lane & 15, lc = (lane >> 4) * 8;

#pragma unroll
    for (int ks = 0; ks < KT; ks++) {
        int k0 = ks * 16;
        unsigned af[2][4];
#pragma unroll
        for (int mi = 0; mi < 2; mi++) {
            unsigned addr = a_base + (unsigned)(((wm0 + mi * 16 + lr) * AP + k0 + lc) * 2);
            ldsm_x4(af[mi][0], af[mi][1], af[mi][2], af[mi][3], addr);
        }
        unsigned bf[4][4];
#pragma unroll
        for (int nj = 0; nj < 4; nj++) {
            unsigned addr = b_base + (unsigned)(((k0 + lr) * 136 + wn0 + nj * 16 + lc) * 2);
            ldsm_x4t(bf[nj][0], bf[nj][1], bf[nj][2], bf[nj][3], addr);
        }
#pragma unroll
        for (int mi = 0; mi < 2; mi++)
#pragma unroll
            for (int nj = 0; nj < 4; nj++) {
                mma16816(acc[mi][2 * nj], af[mi], bf[nj][0], bf[nj][1]);
                mma16816(acc[mi][2 * nj + 1], af[mi], bf[nj][2], bf[nj][3]);
            }
    }

    int gr = lane >> 2, gc = (lane & 3) * 2;
#pragma unroll
    for (int mi = 0; mi < 2; mi++) {
#pragma unroll
        for (int nj8 = 0; nj8 < 8; nj8++) {
            int col = n0 + wn0 + nj8 * 8 + gc;
#pragma unroll
            for (int rr = 0; rr < 2; rr++) {
                int row = m0 + wm0 + mi * 16 + gr + rr * 8;
                if (col + 1 < nreal)
                    *reinterpret_cast<float2*>(C + (size_t)row * ldc + col) =
                        make_float2(acc[mi][nj8][rr * 2], acc[mi][nj8][rr * 2 + 1]);
                else if (col < nreal)
                    C[(size_t)row * ldc + col] = acc[mi][nj8][rr * 2];
            }
        }
    }
}

// ---------------- cvt agg -> fp16 concat (and re-zero agg) ----------------
__global__ void k_cvt_agg() {
    int idx = blockIdx.x * blockDim.x + threadIdx.x;
    if (idx >= N_NODES * KP) return;
    int n = idx / KP, c = idx % KP;
    float v = 0.0f;
    if (c < H) { v = g_agg[n * H + c]; g_agg[n * H + c] = 0.0f; }
    g_ah[n * AHW + c] = __float2half(v);
}

// ---------------- GRU pointwise ----------------
__global__ void k_grupt(const float* __restrict__ bih, const float* __restrict__ bhh) {
    int idx = blockIdx.x * blockDim.x + threadIdx.x;
    if (idx >= N_NODES * KP) return;
    int n = idx / KP, c = idx % KP;
    if (c >= H) { g_ah[n * AHW + KP + c] = __float2half(0.0f); return; }
    const float* G = g_GG + (size_t)n * GGW;
    float r = sigf(G[c] + G[224 + c] + bih[c] + bhh[c]);
    float z = sigf(G[H + c] + G[224 + H + c] + bih[H + c] + bhh[H + c]);
    float nn = tanhf(G[2 * H + c] + bih[2 * H + c] + r * (G[224 + 2 * H + c] + bhh[2 * H + c]));
    float hv = (1.0f - z) * nn + z * g_h[n * H + c];
    g_h[n * H + c] = hv;
    g_ah[n * AHW + KP + c] = __float2half(hv);
}

// ---------------- Set2Set ----------------
#define EVMAX 2048
__global__ __launch_bounds__(256) void k_s2s(const float* __restrict__ Wih,
                                             const float* __restrict__ Whh,
                                             const float* __restrict__ bih,
                                             const float* __restrict__ bhh,
                                             const float* __restrict__ Wout,
                                             const float* __restrict__ bout,
                                             const int* __restrict__ batch,
                                             float* __restrict__ out) {
    extern __shared__ float sm[];
    float* Wa    = sm;
    float* Wb    = Wa + 292 * 73;
    float* bias  = Wb + 292 * 73;
    float* gates = bias + 292;
    float* hh    = gates + 292;
    float* cc    = hh + 73;
    float* rr    = cc + 73;
    float* rsum  = rr + 73;
    float* ev    = rsum + 73;
    float* red   = ev + EVMAX;

    int tid = threadIdx.x;
    int b = blockIdx.x;

    for (int i = tid; i < 292 * 73; i += 256) {
        int g = i / 73, k = i % 73;
        Wa[i] = Wih[(size_t)g * 146 + k] + Whh[(size_t)g * 73 + k];
        Wb[i] = Wih[(size_t)g * 146 + 73 + k];
    }
    for (int i = tid; i < 292; i += 256) bias[i] = bih[i] + bhh[i];
    if (tid < H) { hh[tid] = 0.0f; cc[tid] = 0.0f; rr[tid] = 0.0f; }

    int lo = 0, hi = N_NODES;
    while (lo < hi) { int mid = (lo + hi) >> 1; if (batch[mid] < b) lo = mid + 1; else hi = mid; }
    int s0 = lo;
    hi = N_NODES;
    while (lo < hi) { int mid = (lo + hi) >> 1; if (batch[mid] < b + 1) lo = mid + 1; else hi = mid; }
    int len = lo - s0;
    if (len > EVMAX) len = EVMAX;
    __syncthreads();

    int lane = tid & 31, w = tid >> 5;

    for (int t = 0; t < T_S2S; t++) {
        for (int g = tid; g < 292; g += 256) {
            const float* wa = Wa + g * 73;
            const float* wb = Wb + g * 73;
            float acc = bias[g];
            for (int k = 0; k < H; k++) acc += hh[k] * wa[k] + rr[k] * wb[k];
            gates[g] = acc;
        }
        __syncthreads();
        if (tid < H) {
            float ig = gates[tid], fg = gates[H + tid], gg = gates[2 * H + tid], og = gates[3 * H + tid];
            float c2 = sigf(fg) * cc[tid] + sigf(ig) * tanhf(gg);
            cc[tid] = c2;
            hh[tid] = sigf(og) * tanhf(c2);
        }
        __syncthreads();

        if (len > 0) {
            for (int n = w; n < len; n += 8) {
                const float* hrow = g_h + (size_t)(s0 + n) * H;
                float acc = 0.0f;
                for (int c = lane; c < H; c += 32) acc += hrow[c] * hh[c];
#pragma unroll
                for (int o = 16; o; o >>= 1) acc += __shfl_down_sync(0xffffffffu, acc, o);
                if (lane == 0) ev[n] = acc;
            }
            __syncthreads();
            float m = -INFINITY;
            for (int n = tid; n < len; n += 256) m = fmaxf(m, ev[n]);
#pragma unroll
            for (int o = 16; o; o >>= 1) m = fmaxf(m, __shfl_xor_sync(0xffffffffu, m, o));
            if (lane == 0) red[w] = m;
            __syncthreads();
            if (tid == 0) {
                float mm = red[0];
                for (int i = 1; i < 8; i++) mm = fmaxf(mm, red[i]);
                red[32] = mm;
            }
            __syncthreads();
            m = red[32];
            float s = 0.0f;
            for (int n = tid; n < len; n += 256) { float a = expf(ev[n] - m); ev[n] = a; s += a; }
#pragma unroll
            for (int o = 16; o; o >>= 1) s += __shfl_xor_sync(0xffffffffu, s, o);
            if (lane == 0) red[w] = s;
            __syncthreads();
            if (tid == 0) {
                float ss = 0.0f;
                for (int i = 0; i < 8; i++) ss += red[i];
                red[33] = ss;
            }
            __syncthreads();
            float inv = 1.0f / red[33];
            if (tid < H) rsum[tid] = 0.0f;
            __syncthreads();
            {
                float a0 = 0.0f, a1 = 0.0f, a2 = 0.0f;
                int c0 = lane, c1 = lane + 32, c2 = lane + 64;
                for (int n = w; n < len; n += 8) {
                    float a = ev[n];
                    const float* hrow = g_h + (size_t)(s0 + n) * H;
                    a0 += a * hrow[c0];
                    a1 += a * hrow[c1];
                    if (lane < 9) a2 += a * hrow[c2];
                }
                atomicAdd(&rsum[c0], a0);
                atomicAdd(&rsum[c1], a1);
                if (lane < 9) atomicAdd(&rsum[c2], a2);
            }
            __syncthreads();
            if (tid < H) rr[tid] = rsum[tid] * inv;
            __syncthreads();
        }
    }

    if (tid == 0) {
        float s = bout[0];
        for (int c = 0; c < H; c++) s += hh[c] * Wout[c];
        out[b] = s;
    }
}

// ---------------- launch ----------------
extern "C" void kernel_launch(void* const* d_in, const int* in_sizes, int n_in,
                              void* d_out, int out_size) {
    const float* nf   = (const float*)d_in[0];
    const float* ef   = (const float*)d_in[1];
    const float* Win  = (const float*)d_in[2];
    const float* bin  = (const float*)d_in[3];
    const float* W1   = (const float*)d_in[4];
    const float* b1   = (const float*)d_in[5];
    const float* W2   = (const float*)d_in[6];
    const float* b2   = (const float*)d_in[7];
    const float* gWih = (const float*)d_in[8];
    const float* gWhh = (const float*)d_in[9];
    const float* gbih = (const float*)d_in[10];
    const float* gbhh = (const float*)d_in[11];
    const float* lWih = (const float*)d_in[12];
    const float* lWhh = (const float*)d_in[13];
    const float* lbih = (const float*)d_in[14];
    const float* lbhh = (const float*)d_in[15];
    const float* Wout = (const float*)d_in[16];
    const float* bout = (const float*)d_in[17];
    const int* Esrc   = (const int*)d_in[18];
    const int* Etgt   = (const int*)d_in[19];
    const int* batch  = (const int*)d_in[20];
    float* out = (float*)d_out;

    __half *p_ah, *p_Wgru;
    float *p_GG;
    cudaGetSymbolAddress((void**)&p_ah, g_ah);
    cudaGetSymbolAddress((void**)&p_Wgru, g_Wgru);
    cudaGetSymbolAddress((void**)&p_GG, g_GG);

    const int SMSTEP = (5632 + 2 * 80 * BSP + SRCB * CSP) * 2;   // 86784
    const int SM10 = (128 * 168 + 160 * 136) * 2;                // 86528
    cudaFuncSetAttribute(k_step, cudaFuncAttributeMaxDynamicSharedMemorySize, SMSTEP);
    cudaFuncSetAttribute(k_hgemm<10>, cudaFuncAttributeMaxDynamicSharedMemorySize, SM10);
    size_t s2s_smem = (size_t)(2 * 292 * 73 + 292 + 292 + 4 * 73 + EVMAX + 34) * sizeof(float);
    cudaFuncSetAttribute(k_s2s, cudaFuncAttributeMaxDynamicSharedMemorySize, (int)s2s_smem);

    dim3 gG(4, N_NODES / 128);

    k_prepW2<<<73, 256>>>(W2, b2);                                         // 0
    k_prep<<<NB_H0 + NB_RH, 256>>>(nf, Win, bin, ef, W1, b1);              // 1
    k_scan<<<1, 1024>>>(Esrc);                                              // 2
    k_misc<<<(AHW * GGW + 255) / 256, 256>>>(Esrc, Etgt, gWih, gWhh);      // 3
    k_sortRH<<<(N_EDGES * 40 + 255) / 256, 256>>>();                       // 4

    for (int t = 0; t < T_MP; t++) {
        k_step<<<N_NODES / SRCB, 256, SMSTEP>>>(p_ah + KP);                // 5 (t=0)
        k_cvt_agg<<<(N_NODES * KP + 255) / 256, 256>>>();
        k_hgemm<10><<<gG, 256, SM10>>>(p_ah, AHW, p_Wgru, GGW, p_GG, GGW, 448);
        k_grupt<<<(N_NODES * KP + 255) / 256, 256>>>(gbih, gbhh);
    }

    k_s2s<<<NB, 256, s2s_smem>>>(lWih, lWhh, lbih, lbhh, Wout, bout, batch, out);
}

// round 9
// speedup vs baseline: 1.3254x; 1.3254x over previous
#include <cuda_runtime.h>
#include <cuda_fp16.h>
#include <math.h>

#define N_NODES 8192
#define N_EDGES 32768
#define FN 32
#define FE 16
#define H 73
#define HH (H*H)            // 5329
#define KP 80               // padded K (5 x k16)
#define TW 5402             // T2 logical row width = 73*74
#define TWP 5504            // padded pitch (43*128)
#define G3 219
#define G3P 256
#define GLD 220
#define NB 64
#define T_MP 3
#define T_S2S 12

// ---------------- device scratch ----------------
__device__ float g_h[N_NODES * H];
__device__ __half g_h16[N_NODES * KP];
__device__ float g_RH[N_EDGES * H];               // fp32 edge MLP output
__device__ float g_agg[N_NODES * H];
__device__ __half g_T2[(size_t)N_NODES * TWP];    // 90 MB fp16
__device__ __half g_W2e[KP * TWP];
__device__ __half g_WihT[KP * G3P];
__device__ __half g_WhhT[KP * G3P];
__device__ float g_GG1[N_NODES * GLD];
__device__ float g_GG2[N_NODES * GLD];
__device__ int g_off[N_NODES + 1];
__device__ int g_cur[N_NODES];
__device__ int g_eord[N_EDGES];
__device__ int g_tgtS[N_EDGES];

__device__ __forceinline__ float sigf(float x) { return 1.0f / (1.0f + expf(-x)); }

__device__ __forceinline__ void ldsm_x4(unsigned &r0, unsigned &r1, unsigned &r2, unsigned &r3, unsigned addr) {
    asm volatile("ldmatrix.sync.aligned.m8n8.x4.shared.b16 {%0,%1,%2,%3},[%4];"
                 : "=r"(r0), "=r"(r1), "=r"(r2), "=r"(r3) : "r"(addr));
}
__device__ __forceinline__ void ldsm_x4t(unsigned &r0, unsigned &r1, unsigned &r2, unsigned &r3, unsigned addr) {
    asm volatile("ldmatrix.sync.aligned.m8n8.x4.trans.shared.b16 {%0,%1,%2,%3},[%4];"
                 : "=r"(r0), "=r"(r1), "=r"(r2), "=r"(r3) : "r"(addr));
}
__device__ __forceinline__ void mma16816(float* d, const unsigned* a, unsigned b0, unsigned b1) {
    asm volatile("mma.sync.aligned.m16n8k16.row.col.f32.f16.f16.f32 "
                 "{%0,%1,%2,%3},{%4,%5,%6,%7},{%8,%9},{%0,%1,%2,%3};"
                 : "+f"(d[0]), "+f"(d[1]), "+f"(d[2]), "+f"(d[3])
                 : "r"(a[0]), "r"(a[1]), "r"(a[2]), "r"(a[3]), "r"(b0), "r"(b1));
}

// ---------------- prepW2: smem-tiled transpose into W2e ----------------
__global__ __launch_bounds__(256) void k_prepW2(const float* __restrict__ W2,
                                                const float* __restrict__ b2) {
    __shared__ float tile[74 * 73];
    int i = blockIdx.x;
    int tid = threadIdx.x;
    for (int idx = tid; idx < 74 * 73; idx += 256) {
        int kk = idx / 73, j = idx % 73;
        tile[idx] = (kk < H) ? W2[(size_t)kk * HH + i * H + j] : b2[i * H + j];
    }
    __syncthreads();
    for (int idx = tid; idx < 73 * 74; idx += 256) {
        int j = idx / 74, kk = idx % 74;
        g_W2e[(size_t)j * TWP + i * 74 + kk] = __float2half(tile[kk * 73 + j]);
    }
    const int PAD1 = 7 * TWP, PADT = PAD1 + 73 * 102;
    for (int p = blockIdx.x * 256 + tid; p < PADT; p += 73 * 256) {
        int j, c;
        if (p < PAD1) { j = 73 + p / TWP; c = p % TWP; }
        else { int q = p - PAD1; j = q / 102; c = TW + q % 102; }
        g_W2e[(size_t)j * TWP + c] = __float2half(0.0f);
    }
}

// ---------------- prep: h0 (+agg zero) and RH ----------------
#define NB_H0 ((N_NODES * KP) / 256)      // 2560
#define NB_RH ((N_EDGES * H) / 256)       // 9344
__global__ void k_prep(const float* __restrict__ nf, const float* __restrict__ Win,
                       const float* __restrict__ bin, const float* __restrict__ ef,
                       const float* __restrict__ W1, const float* __restrict__ b1) {
    int b = blockIdx.x;
    int tid = threadIdx.x;
    if (b < NB_H0) {
        int idx = b * 256 + tid;
        if (idx < N_NODES * H) g_agg[idx] = 0.0f;
        int n = idx / KP, c = idx % KP;
        if (c >= H) { g_h16[idx] = __float2half(0.0f); return; }
        const float* x = nf + n * FN;
        float acc = bin[c];
#pragma unroll
        for (int k = 0; k < FN; k++) acc += x[k] * Win[k * H + c];
        g_h[n * H + c] = acc;
        g_h16[idx] = __float2half(acc);
    } else {
        int idx = (b - NB_H0) * 256 + tid;
        int e = idx / H, c = idx % H;
        const float* x = ef + e * FE;
        float acc = b1[c];
#pragma unroll
        for (int k = 0; k < FE; k++) acc += x[k] * W1[k * H + c];
        g_RH[idx] = fmaxf(acc, 0.0f);
    }
}

// ---------------- scan with in-kernel histogram ----------------
__global__ __launch_bounds__(1024) void k_scan(const int* __restrict__ Esrc) {
    __shared__ int hist[N_NODES];
    __shared__ int sm_[1024];
    int tid = threadIdx.x;
    for (int i = tid; i < N_NODES; i += 1024) hist[i] = 0;
    __syncthreads();
    for (int e = tid; e < N_EDGES; e += 1024) atomicAdd(&hist[Esrc[e]], 1);
    __syncthreads();
    int base = tid * 8;
    int v[8], s = 0;
#pragma unroll
    for (int i = 0; i < 8; i++) { v[i] = hist[base + i]; s += v[i]; }
    sm_[tid] = s;
    __syncthreads();
    for (int off = 1; off < 1024; off <<= 1) {
        int t = (tid >= off) ? sm_[tid - off] : 0;
        __syncthreads();
        sm_[tid] += t;
        __syncthreads();
    }
    int run = sm_[tid] - s;
#pragma unroll
    for (int i = 0; i < 8; i++) {
        g_off[base + i] = run;
        g_cur[base + i] = run;
        run += v[i];
    }
    if (tid == 1023) g_off[N_NODES] = run;
}

// ---------------- misc: scatter edges + transposed GRU weights ----------------
__global__ void k_misc(const int* __restrict__ Esrc, const int* __restrict__ Etgt,
                       const float* __restrict__ Wih, const float* __restrict__ Whh) {
    int idx = blockIdx.x * blockDim.x + threadIdx.x;
    if (idx < N_EDGES) {
        int p = atomicAdd(&g_cur[Esrc[idx]], 1);
        g_eord[p] = idx;
        g_tgtS[p] = Etgt[idx];
    }
    if (idx < KP * G3P) {
        int k = idx >> 8, g = idx & 255;
        float a = 0.0f, bb = 0.0f;
        if (k < H && g < G3) { a = Wih[(size_t)g * H + k]; bb = Whh[(size_t)g * H + k]; }
        g_WihT[idx] = __float2half(a);
        g_WhhT[idx] = __float2half(bb);
    }
}

// ---------------- T2 GEMM: T2[M,TWP] = h16[M,80] @ W2e[80,TWP], fp16 out ----------
// smem-staged coalesced stores in the epilogue.
__global__ __launch_bounds__(256) void k_tgemm(const __half* __restrict__ A) {
    __shared__ __align__(16) __half sm_u[22144];   // 44288 B
    __half* As = sm_u;                 // [128][88]
    __half* Bs = sm_u + 128 * 88;      // [80][136]
    __half* Cs = sm_u;                 // [128][136] alias (34816 B)
    int tid = threadIdx.x;
    int m0 = blockIdx.y * 128;
    int n0 = blockIdx.x * 128;

    for (int idx = tid; idx < 1280; idx += 256) {
        int r = idx / 10, c = idx % 10;
        *reinterpret_cast<uint4*>(&As[r * 88 + c * 8]) =
            *reinterpret_cast<const uint4*>(A + (size_t)(m0 + r) * KP + c * 8);
    }
    for (int idx = tid; idx < 1280; idx += 256) {
        int k = idx >> 4, c = idx & 15;
        *reinterpret_cast<uint4*>(&Bs[k * 136 + c * 8]) =
            *reinterpret_cast<const uint4*>(g_W2e + (size_t)k * TWP + n0 + c * 8);
    }
    __syncthreads();

    int wid = tid >> 5, lane = tid & 31;
    int wm0 = (wid & 3) * 32;
    int wn0 = (wid >> 2) * 64;

    float acc[2][8][4];
#pragma unroll
    for (int i = 0; i < 2; i++)
#pragma unroll
        for (int j = 0; j < 8; j++)
#pragma unroll
            for (int q = 0; q < 4; q++) acc[i][j][q] = 0.0f;

    unsigned a_base = (unsigned)__cvta_generic_to_shared(As);
    unsigned b_base = (unsigned)__cvta_generic_to_shared(Bs);
    int lr = lane & 15, lc = (lane >> 4) * 8;

#pragma unroll
    for (int ks = 0; ks < 5; ks++) {
        int k0 = ks * 16;
        unsigned af[2][4];
#pragma unroll
        for (int mi = 0; mi < 2; mi++) {
            unsigned addr = a_base + (unsigned)(((wm0 + mi * 16 + lr) * 88 + k0 + lc) * 2);
            ldsm_x4(af[mi][0], af[mi][1], af[mi][2], af[mi][3], addr);
        }
        unsigned bf[4][4];
#pragma unroll
        for (int nj = 0; nj < 4; nj++) {
            unsigned addr = b_base + (unsigned)(((k0 + lr) * 136 + wn0 + nj * 16 + lc) * 2);
            ldsm_x4t(bf[nj][0], bf[nj][1], bf[nj][2], bf[nj][3], addr);
        }
#pragma unroll
        for (int mi = 0; mi < 2; mi++)
#pragma unroll
            for (int nj = 0; nj < 4; nj++) {
                mma16816(acc[mi][2 * nj], af[mi], bf[nj][0], bf[nj][1]);
                mma16816(acc[mi][2 * nj + 1], af[mi], bf[nj][2], bf[nj][3]);
            }
    }
    __syncthreads();   // smem reads done; reuse as C staging

    int gr = lane >> 2, gc = (lane & 3) * 2;
#pragma unroll
    for (int mi = 0; mi < 2; mi++) {
#pragma unroll
        for (int nj8 = 0; nj8 < 8; nj8++) {
            int col = wn0 + nj8 * 8 + gc;
#pragma unroll
            for (int rr = 0; rr < 2; rr++) {
                int row = wm0 + mi * 16 + gr + rr * 8;
                *reinterpret_cast<__half2*>(&Cs[row * 136 + col]) =
                    __floats2half2_rn(acc[mi][nj8][rr * 2], acc[mi][nj8][rr * 2 + 1]);
            }
        }
    }
    __syncthreads();

    // coalesced STG.128: 128 rows x 16 uint4
    for (int idx = tid; idx < 2048; idx += 256) {
        int r = idx >> 4, c = idx & 15;
        *reinterpret_cast<uint4*>(g_T2 + (size_t)(m0 + r) * TWP + n0 + c * 8) =
            *reinterpret_cast<const uint4*>(&Cs[r * 136 + c * 8]);
    }
}

// ---------------- messages (R4-proven): block per src, 96 threads ----------------
__global__ __launch_bounds__(96) void k_msg2() {
    int src = blockIdx.x;
    int s0 = g_off[src], s1 = g_off[src + 1];
    if (s0 == s1) return;
    __shared__ float rh[8][H];
    __shared__ int tgts[8];
    int tid = threadIdx.x;
    const __half* trow = g_T2 + (size_t)src * TWP;

    for (int base = s0; base < s1; base += 8) {
        int ne = min(8, s1 - base);
        for (int idx = tid; idx < ne * H; idx += 96) {
            int el = idx / H, k = idx - el * H;
            rh[el][k] = g_RH[(size_t)g_eord[base + el] * H + k];
        }
        if (tid < ne) tgts[tid] = g_tgtS[base + tid];
        __syncthreads();
        if (tid < H) {
            const __half* tp = trow + tid * (H + 1);
            float bterm = __half2float(tp[H]);
            float acc[8];
#pragma unroll
            for (int e = 0; e < 8; e++) acc[e] = bterm;
#pragma unroll 4
            for (int k2 = 0; k2 < 36; k2++) {
                float2 vf = __half22float2(*reinterpret_cast<const __half2*>(tp + 2 * k2));
#pragma unroll
                for (int e = 0; e < 8; e++)
                    if (e < ne) acc[e] += rh[e][2 * k2] * vf.x + rh[e][2 * k2 + 1] * vf.y;
            }
            float v72 = __half2float(tp[72]);
#pragma unroll
            for (int e = 0; e < 8; e++)
                if (e < ne) {
                    acc[e] += rh[e][72] * v72;
                    atomicAdd(&g_agg[(size_t)tgts[e] * H + tid], acc[e]);
                }
        }
        __syncthreads();
    }
}

// ---------------- gates GEMM: C[M,219] = A[M,80] @ B[80,256], fp32 out -----------
// AF32=1: A is fp32 with row width H (g_agg), converted during smem fill.
template <int AF32>
__global__ __launch_bounds__(256) void k_ggemm(const void* __restrict__ Av,
                                               const __half* __restrict__ B,
                                               float* __restrict__ C) {
    __shared__ __align__(16) __half As[128][88];
    __shared__ __align__(16) __half Bs[80][136];
    int tid = threadIdx.x;
    int m0 = blockIdx.y * 128;
    int n0 = blockIdx.x * 128;

    if (AF32) {
        const float* Af = (const float*)Av;
        for (int idx = tid; idx < 128 * KP; idx += 256) {
            int r = idx / KP, c = idx - r * KP;
            float v = (c < H) ? Af[(size_t)(m0 + r) * H + c] : 0.0f;
            As[r][c] = __float2half(v);
        }
    } else {
        const __half* Ah = (const __half*)Av;
        for (int idx = tid; idx < 1280; idx += 256) {
            int r = idx / 10, c = idx % 10;
            *reinterpret_cast<uint4*>(&As[r][c * 8]) =
                *reinterpret_cast<const uint4*>(Ah + (size_t)(m0 + r) * KP + c * 8);
        }
    }
    for (int idx = tid; idx < 1280; idx += 256) {
        int k = idx >> 4, c = idx & 15;
        *reinterpret_cast<uint4*>(&Bs[k][c * 8]) =
            *reinterpret_cast<const uint4*>(B + (size_t)k * G3P + n0 + c * 8);
    }
    __syncthreads();

    int wid = tid >> 5, lane = tid & 31;
    int wm0 = (wid & 3) * 32;
    int wn0 = (wid >> 2) * 64;

    float acc[2][8][4];
#pragma unroll
    for (int i = 0; i < 2; i++)
#pragma unroll
        for (int j = 0; j < 8; j++)
#pragma unroll
            for (int q = 0; q < 4; q++) acc[i][j][q] = 0.0f;

    unsigned a_base = (unsigned)__cvta_generic_to_shared(&As[0][0]);
    unsigned b_base = (unsigned)__cvta_generic_to_shared(&Bs[0][0]);
    int lr = lane & 15, lc = (lane >> 4) * 8;

#pragma unroll
    for (int ks = 0; ks < 5; ks++) {
        int k0 = ks * 16;
        unsigned af[2][4];
#pragma unroll
        for (int mi = 0; mi < 2; mi++) {
            unsigned addr = a_base + (unsigned)(((wm0 + mi * 16 + lr) * 88 + k0 + lc) * 2);
            ldsm_x4(af[mi][0], af[mi][1], af[mi][2], af[mi][3], addr);
        }
        unsigned bf[4][4];
#pragma unroll
        for (int nj = 0; nj < 4; nj++) {
            unsigned addr = b_base + (unsigned)(((k0 + lr) * 136 + wn0 + nj * 16 + lc) * 2);
            ldsm_x4t(bf[nj][0], bf[nj][1], bf[nj][2], bf[nj][3], addr);
        }
#pragma unroll
        for (int mi = 0; mi < 2; mi++)
#pragma unroll
            for (int nj = 0; nj < 4; nj++) {
                mma16816(acc[mi][2 * nj], af[mi], bf[nj][0], bf[nj][1]);
                mma16816(acc[mi][2 * nj + 1], af[mi], bf[nj][2], bf[nj][3]);
            }
    }

    int gr = lane >> 2, gc = (lane & 3) * 2;
#pragma unroll
    for (int mi = 0; mi < 2; mi++) {
#pragma unroll
        for (int nj8 = 0; nj8 < 8; nj8++) {
            int col = n0 + wn0 + nj8 * 8 + gc;
#pragma unroll
            for (int rr = 0; rr < 2; rr++) {
                int row = m0 + wm0 + mi * 16 + gr + rr * 8;
                if (col + 1 < G3)
                    *reinterpret_cast<float2*>(C + (size_t)row * GLD + col) =
                        make_float2(acc[mi][nj8][rr * 2], acc[mi][nj8][rr * 2 + 1]);
                else if (col < G3)
                    C[(size_t)row * GLD + col] = acc[mi][nj8][rr * 2];
            }
        }
    }
}

// ---------------- GRU pointwise (+ agg re-zero for next step) ----------------
__global__ void k_grupt(const float* __restrict__ bih, const float* __restrict__ bhh) {
    int idx = blockIdx.x * blockDim.x + threadIdx.x;
    if (idx >= N_NODES * KP) return;
    int n = idx / KP, c = idx % KP;
    if (c >= H) { g_h16[idx] = __float2half(0.0f); return; }
    const float* G1 = g_GG1 + (size_t)n * GLD;
    const float* G2 = g_GG2 + (size_t)n * GLD;
    float r = sigf(G1[c] + G2[c] + bih[c] + bhh[c]);
    float z = sigf(G1[H + c] + G2[H + c] + bih[H + c] + bhh[H + c]);
    float nn = tanhf(G1[2 * H + c] + bih[2 * H + c] + r * (G2[2 * H + c] + bhh[2 * H + c]));
    float hv = (1.0f - z) * nn + z * g_h[n * H + c];
    g_h[n * H + c] = hv;
    g_h16[idx] = __float2half(hv);
    g_agg[n * H + c] = 0.0f;
}

// ---------------- Set2Set ----------------
#define EVMAX 2048
__global__ __launch_bounds__(256) void k_s2s(const float* __restrict__ Wih,
                                             const float* __restrict__ Whh,
                                             const float* __restrict__ bih,
                                             const float* __restrict__ bhh,
                                             const float* __restrict__ Wout,
                                             const float* __restrict__ bout,
                                             const int* __restrict__ batch,
                                             float* __restrict__ out) {
    extern __shared__ float sm[];
    float* Wa    = sm;
    float* Wb    = Wa + 292 * 73;
    float* bias  = Wb + 292 * 73;
    float* gates = bias + 292;
    float* hh    = gates + 292;
    float* cc    = hh + 73;
    float* rr    = cc + 73;
    float* rsum  = rr + 73;
    float* ev    = rsum + 73;
    float* red   = ev + EVMAX;

    int tid = threadIdx.x;
    int b = blockIdx.x;

    for (int i = tid; i < 292 * 73; i += 256) {
        int g = i / 73, k = i % 73;
        Wa[i] = Wih[(size_t)g * 146 + k] + Whh[(size_t)g * 73 + k];
        Wb[i] = Wih[(size_t)g * 146 + 73 + k];
    }
    for (int i = tid; i < 292; i += 256) bias[i] = bih[i] + bhh[i];
    if (tid < H) { hh[tid] = 0.0f; cc[tid] = 0.0f; rr[tid] = 0.0f; }

    int lo = 0, hi = N_NODES;
    while (lo < hi) { int mid = (lo + hi) >> 1; if (batch[mid] < b) lo = mid + 1; else hi = mid; }
    int s0 = lo;
    hi = N_NODES;
    while (lo < hi) { int mid = (lo + hi) >> 1; if (batch[mid] < b + 1) lo = mid + 1; else hi = mid; }
    int len = lo - s0;
    if (len > EVMAX) len = EVMAX;
    __syncthreads();

    int lane = tid & 31, w = tid >> 5;

    for (int t = 0; t < T_S2S; t++) {
        for (int g = tid; g < 292; g += 256) {
            const float* wa = Wa + g * 73;
            const float* wb = Wb + g * 73;
            float acc = bias[g];
            for (int k = 0; k < H; k++) acc += hh[k] * wa[k] + rr[k] * wb[k];
            gates[g] = acc;
        }
        __syncthreads();
        if (tid < H) {
            float ig = gates[tid], fg = gates[H + tid], gg = gates[2 * H + tid], og = gates[3 * H + tid];
            float c2 = sigf(fg) * cc[tid] + sigf(ig) * tanhf(gg);
            cc[tid] = c2;
            hh[tid] = sigf(og) * tanhf(c2);
        }
        __syncthreads();

        if (len > 0) {
            for (int n = w; n < len; n += 8) {
                const float* hrow = g_h + (size_t)(s0 + n) * H;
                float acc = 0.0f;
                for (int c = lane; c < H; c += 32) acc += hrow[c] * hh[c];
#pragma unroll
                for (int o = 16; o; o >>= 1) acc += __shfl_down_sync(0xffffffffu, acc, o);
                if (lane == 0) ev[n] = acc;
            }
            __syncthreads();
            float m = -INFINITY;
            for (int n = tid; n < len; n += 256) m = fmaxf(m, ev[n]);
#pragma unroll
            for (int o = 16; o; o >>= 1) m = fmaxf(m, __shfl_xor_sync(0xffffffffu, m, o));
            if (lane == 0) red[w] = m;
            __syncthreads();
            if (tid == 0) {
                float mm = red[0];
                for (int i = 1; i < 8; i++) mm = fmaxf(mm, red[i]);
                red[32] = mm;
            }
            __syncthreads();
            m = red[32];
            float s = 0.0f;
            for (int n = tid; n < len; n += 256) { float a = expf(ev[n] - m); ev[n] = a; s += a; }
#pragma unroll
            for (int o = 16; o; o >>= 1) s += __shfl_xor_sync(0xffffffffu, s, o);
            if (lane == 0) red[w] = s;
            __syncthreads();
            if (tid == 0) {
                float ss = 0.0f;
                for (int i = 0; i < 8; i++) ss += red[i];
                red[33] = ss;
            }
            __syncthreads();
            float inv = 1.0f / red[33];
            if (tid < H) rsum[tid] = 0.0f;
            __syncthreads();
            {
                float a0 = 0.0f, a1 = 0.0f, a2 = 0.0f;
                int c0 = lane, c1 = lane + 32, c2 = lane + 64;
                for (int n = w; n < len; n += 8) {
                    float a = ev[n];
                    const float* hrow = g_h + (size_t)(s0 + n) * H;
                    a0 += a * hrow[c0];
                    a1 += a * hrow[c1];
                    if (lane < 9) a2 += a * hrow[c2];
                }
                atomicAdd(&rsum[c0], a0);
                atomicAdd(&rsum[c1], a1);
                if (lane < 9) atomicAdd(&rsum[c2], a2);
            }
            __syncthreads();
            if (tid < H) rr[tid] = rsum[tid] * inv;
            __syncthreads();
        }
    }

    if (tid == 0) {
        float s = bout[0];
        for (int c = 0; c < H; c++) s += hh[c] * Wout[c];
        out[b] = s;
    }
}

// ---------------- launch ----------------
extern "C" void kernel_launch(void* const* d_in, const int* in_sizes, int n_in,
                              void* d_out, int out_size) {
    const float* nf   = (const float*)d_in[0];
    const float* ef   = (const float*)d_in[1];
    const float* Win  = (const float*)d_in[2];
    const float* bin  = (const float*)d_in[3];
    const float* W1   = (const float*)d_in[4];
    const float* b1   = (const float*)d_in[5];
    const float* W2   = (const float*)d_in[6];
    const float* b2   = (const float*)d_in[7];
    const float* gWih = (const float*)d_in[8];
    const float* gWhh = (const float*)d_in[9];
    const float* gbih = (const float*)d_in[10];
    const float* gbhh = (const float*)d_in[11];
    const float* lWih = (const float*)d_in[12];
    const float* lWhh = (const float*)d_in[13];
    const float* lbih = (const float*)d_in[14];
    const float* lbhh = (const float*)d_in[15];
    const float* Wout = (const float*)d_in[16];
    const float* bout = (const float*)d_in[17];
    const int* Esrc   = (const int*)d_in[18];
    const int* Etgt   = (const int*)d_in[19];
    const int* batch  = (const int*)d_in[20];
    float* out = (float*)d_out;

    __half *p_h16, *p_WihT, *p_WhhT;
    float *p_agg, *p_GG1, *p_GG2;
    cudaGetSymbolAddress((void**)&p_h16, g_h16);
    cudaGetSymbolAddress((void**)&p_WihT, g_WihT);
    cudaGetSymbolAddress((void**)&p_WhhT, g_WhhT);
    cudaGetSymbolAddress((void**)&p_agg, g_agg);
    cudaGetSymbolAddress((void**)&p_GG1, g_GG1);
    cudaGetSymbolAddress((void**)&p_GG2, g_GG2);

    size_t s2s_smem = (size_t)(2 * 292 * 73 + 292 + 292 + 4 * 73 + EVMAX + 34) * sizeof(float);
    cudaFuncSetAttribute(k_s2s, cudaFuncAttributeMaxDynamicSharedMemorySize, (int)s2s_smem);

    dim3 gT(TWP / 128, N_NODES / 128);   // 43 x 64
    dim3 gG(2, N_NODES / 128);           // 2 x 64

    k_prepW2<<<73, 256>>>(W2, b2);                                    // 0
    k_prep<<<NB_H0 + NB_RH, 256>>>(nf, Win, bin, ef, W1, b1);         // 1
    k_scan<<<1, 1024>>>(Esrc);                                         // 2
    k_misc<<<(N_EDGES + 255) / 256, 256>>>(Esrc, Etgt, gWih, gWhh);   // 3

    for (int t = 0; t < T_MP; t++) {
        k_tgemm<<<gT, 256>>>(p_h16);                                   // 4 (t=0)
        k_msg2<<<N_NODES, 96>>>();                                     // 5 (t=0)
        k_ggemm<1><<<gG, 256>>>(p_agg, p_WihT, p_GG1);
        k_ggemm<0><<<gG, 256>>>(p_h16, p_WhhT, p_GG2);
        k_grupt<<<(N_NODES * KP + 255) / 256, 256>>>(gbih, gbhh);
    }

    k_s2s<<<NB, 256, s2s_smem>>>(lWih, lWhh, lbih, lbhh, Wout, bout, batch, out);
}

// round 10
// speedup vs baseline: 1.3285x; 1.0024x over previous
#include <cuda_runtime.h>
#include <cuda_fp16.h>
#include <math.h>

#define N_NODES 8192
#define N_EDGES 32768
#define FN 32
#define FE 16
#define H 73
#define HH (H*H)            // 5329
#define KP 80               // padded K (5 x k16)
#define TW 5402             // T2 logical row width = 73*74
#define TWP 5504            // padded pitch (43*128)
#define G3 219
#define G3P 256
#define GLD 220
#define NB 64
#define T_MP 3
#define T_S2S 12

// ---------------- device scratch ----------------
__device__ float g_h[N_NODES * H];
__device__ __half g_h16[N_NODES * KP];
__device__ float g_RH[N_EDGES * H];               // fp32 edge MLP output
__device__ float g_agg[N_NODES * H];
__device__ __half g_T2[(size_t)N_NODES * TWP];    // 90 MB fp16
__device__ __half g_W2e[KP * TWP];
__device__ __half g_WihT[KP * G3P];
__device__ __half g_WhhT[KP * G3P];
__device__ float g_GG1[N_NODES * GLD];
__device__ float g_GG2[N_NODES * GLD];
__device__ int g_off[N_NODES + 1];
__device__ int g_cur[N_NODES];
__device__ int g_eord[N_EDGES];
__device__ int g_tgtS[N_EDGES];

__device__ __forceinline__ float sigf(float x) { return 1.0f / (1.0f + expf(-x)); }

__device__ __forceinline__ void ldsm_x4(unsigned &r0, unsigned &r1, unsigned &r2, unsigned &r3, unsigned addr) {
    asm volatile("ldmatrix.sync.aligned.m8n8.x4.shared.b16 {%0,%1,%2,%3},[%4];"
                 : "=r"(r0), "=r"(r1), "=r"(r2), "=r"(r3) : "r"(addr));
}
__device__ __forceinline__ void ldsm_x4t(unsigned &r0, unsigned &r1, unsigned &r2, unsigned &r3, unsigned addr) {
    asm volatile("ldmatrix.sync.aligned.m8n8.x4.trans.shared.b16 {%0,%1,%2,%3},[%4];"
                 : "=r"(r0), "=r"(r1), "=r"(r2), "=r"(r3) : "r"(addr));
}
__device__ __forceinline__ void mma16816(float* d, const unsigned* a, unsigned b0, unsigned b1) {
    asm volatile("mma.sync.aligned.m16n8k16.row.col.f32.f16.f16.f32 "
                 "{%0,%1,%2,%3},{%4,%5,%6,%7},{%8,%9},{%0,%1,%2,%3};"
                 : "+f"(d[0]), "+f"(d[1]), "+f"(d[2]), "+f"(d[3])
                 : "r"(a[0]), "r"(a[1]), "r"(a[2]), "r"(a[3]), "r"(b0), "r"(b1));
}

// ---------------- prepW2: smem-tiled transpose into W2e ----------------
__global__ __launch_bounds__(256) void k_prepW2(const float* __restrict__ W2,
                                                const float* __restrict__ b2) {
    __shared__ float tile[74 * 73];
    int i = blockIdx.x;
    int tid = threadIdx.x;
    for (int idx = tid; idx < 74 * 73; idx += 256) {
        int kk = idx / 73, j = idx % 73;
        tile[idx] = (kk < H) ? W2[(size_t)kk * HH + i * H + j] : b2[i * H + j];
    }
    __syncthreads();
    for (int idx = tid; idx < 73 * 74; idx += 256) {
        int j = idx / 74, kk = idx % 74;
        g_W2e[(size_t)j * TWP + i * 74 + kk] = __float2half(tile[kk * 73 + j]);
    }
    const int PAD1 = 7 * TWP, PADT = PAD1 + 73 * 102;
    for (int p = blockIdx.x * 256 + tid; p < PADT; p += 73 * 256) {
        int j, c;
        if (p < PAD1) { j = 73 + p / TWP; c = p % TWP; }
        else { int q = p - PAD1; j = q / 102; c = TW + q % 102; }
        g_W2e[(size_t)j * TWP + c] = __float2half(0.0f);
    }
}

// ---------------- prep: h0 (+agg zero) and RH ----------------
#define NB_H0 ((N_NODES * KP) / 256)      // 2560
#define NB_RH ((N_EDGES * H) / 256)       // 9344
__global__ void k_prep(const float* __restrict__ nf, const float* __restrict__ Win,
                       const float* __restrict__ bin, const float* __restrict__ ef,
                       const float* __restrict__ W1, const float* __restrict__ b1) {
    int b = blockIdx.x;
    int tid = threadIdx.x;
    if (b < NB_H0) {
        int idx = b * 256 + tid;
        if (idx < N_NODES * H) g_agg[idx] = 0.0f;
        int n = idx / KP, c = idx % KP;
        if (c >= H) { g_h16[idx] = __float2half(0.0f); return; }
        const float* x = nf + n * FN;
        float acc = bin[c];
#pragma unroll
        for (int k = 0; k < FN; k++) acc += x[k] * Win[k * H + c];
        g_h[n * H + c] = acc;
        g_h16[idx] = __float2half(acc);
    } else {
        int idx = (b - NB_H0) * 256 + tid;
        int e = idx / H, c = idx % H;
        const float* x = ef + e * FE;
        float acc = b1[c];
#pragma unroll
        for (int k = 0; k < FE; k++) acc += x[k] * W1[k * H + c];
        g_RH[idx] = fmaxf(acc, 0.0f);
    }
}

// ---------------- scan with in-kernel histogram ----------------
__global__ __launch_bounds__(1024) void k_scan(const int* __restrict__ Esrc) {
    __shared__ int hist[N_NODES];
    __shared__ int sm_[1024];
    int tid = threadIdx.x;
    for (int i = tid; i < N_NODES; i += 1024) hist[i] = 0;
    __syncthreads();
    for (int e = tid; e < N_EDGES; e += 1024) atomicAdd(&hist[Esrc[e]], 1);
    __syncthreads();
    int base = tid * 8;
    int v[8], s = 0;
#pragma unroll
    for (int i = 0; i < 8; i++) { v[i] = hist[base + i]; s += v[i]; }
    sm_[tid] = s;
    __syncthreads();
    for (int off = 1; off < 1024; off <<= 1) {
        int t = (tid >= off) ? sm_[tid - off] : 0;
        __syncthreads();
        sm_[tid] += t;
        __syncthreads();
    }
    int run = sm_[tid] - s;
#pragma unroll
    for (int i = 0; i < 8; i++) {
        g_off[base + i] = run;
        g_cur[base + i] = run;
        run += v[i];
    }
    if (tid == 1023) g_off[N_NODES] = run;
}

// ---------------- misc: scatter edges + transposed GRU weights ----------------
__global__ void k_misc(const int* __restrict__ Esrc, const int* __restrict__ Etgt,
                       const float* __restrict__ Wih, const float* __restrict__ Whh) {
    int idx = blockIdx.x * blockDim.x + threadIdx.x;
    if (idx < N_EDGES) {
        int p = atomicAdd(&g_cur[Esrc[idx]], 1);
        g_eord[p] = idx;
        g_tgtS[p] = Etgt[idx];
    }
    if (idx < KP * G3P) {
        int k = idx >> 8, g = idx & 255;
        float a = 0.0f, bb = 0.0f;
        if (k < H && g < G3) { a = Wih[(size_t)g * H + k]; bb = Whh[(size_t)g * H + k]; }
        g_WihT[idx] = __float2half(a);
        g_WhhT[idx] = __float2half(bb);
    }
}

// ---------------- T2 GEMM: T2[M,TWP] = h16[M,80] @ W2e[80,TWP], fp16 out ----------
__global__ __launch_bounds__(256) void k_tgemm(const __half* __restrict__ A) {
    __shared__ __align__(16) __half sm_u[22144];   // 44288 B
    __half* As = sm_u;                 // [128][88]
    __half* Bs = sm_u + 128 * 88;      // [80][136]
    __half* Cs = sm_u;                 // [128][136] alias
    int tid = threadIdx.x;
    int m0 = blockIdx.y * 128;
    int n0 = blockIdx.x * 128;

    for (int idx = tid; idx < 1280; idx += 256) {
        int r = idx / 10, c = idx % 10;
        *reinterpret_cast<uint4*>(&As[r * 88 + c * 8]) =
            *reinterpret_cast<const uint4*>(A + (size_t)(m0 + r) * KP + c * 8);
    }
    for (int idx = tid; idx < 1280; idx += 256) {
        int k = idx >> 4, c = idx & 15;
        *reinterpret_cast<uint4*>(&Bs[k * 136 + c * 8]) =
            *reinterpret_cast<const uint4*>(g_W2e + (size_t)k * TWP + n0 + c * 8);
    }
    __syncthreads();

    int wid = tid >> 5, lane = tid & 31;
    int wm0 = (wid & 3) * 32;
    int wn0 = (wid >> 2) * 64;

    float acc[2][8][4];
#pragma unroll
    for (int i = 0; i < 2; i++)
#pragma unroll
        for (int j = 0; j < 8; j++)
#pragma unroll
            for (int q = 0; q < 4; q++) acc[i][j][q] = 0.0f;

    unsigned a_base = (unsigned)__cvta_generic_to_shared(As);
    unsigned b_base = (unsigned)__cvta_generic_to_shared(Bs);
    int lr = lane & 15, lc = (lane >> 4) * 8;

#pragma unroll
    for (int ks = 0; ks < 5; ks++) {
        int k0 = ks * 16;
        unsigned af[2][4];
#pragma unroll
        for (int mi = 0; mi < 2; mi++) {
            unsigned addr = a_base + (unsigned)(((wm0 + mi * 16 + lr) * 88 + k0 + lc) * 2);
            ldsm_x4(af[mi][0], af[mi][1], af[mi][2], af[mi][3], addr);
        }
        unsigned bf[4][4];
#pragma unroll
        for (int nj = 0; nj < 4; nj++) {
            unsigned addr = b_base + (unsigned)(((k0 + lr) * 136 + wn0 + nj * 16 + lc) * 2);
            ldsm_x4t(bf[nj][0], bf[nj][1], bf[nj][2], bf[nj][3], addr);
        }
#pragma unroll
        for (int mi = 0; mi < 2; mi++)
#pragma unroll
            for (int nj = 0; nj < 4; nj++) {
                mma16816(acc[mi][2 * nj], af[mi], bf[nj][0], bf[nj][1]);
                mma16816(acc[mi][2 * nj + 1], af[mi], bf[nj][2], bf[nj][3]);
            }
    }
    __syncthreads();

    int gr = lane >> 2, gc = (lane & 3) * 2;
#pragma unroll
    for (int mi = 0; mi < 2; mi++) {
#pragma unroll
        for (int nj8 = 0; nj8 < 8; nj8++) {
            int col = wn0 + nj8 * 8 + gc;
#pragma unroll
            for (int rr = 0; rr < 2; rr++) {
                int row = wm0 + mi * 16 + gr + rr * 8;
                *reinterpret_cast<__half2*>(&Cs[row * 136 + col]) =
                    __floats2half2_rn(acc[mi][nj8][rr * 2], acc[mi][nj8][rr * 2 + 1]);
            }
        }
    }
    __syncthreads();

    for (int idx = tid; idx < 2048; idx += 256) {
        int r = idx >> 4, c = idx & 15;
        *reinterpret_cast<uint4*>(g_T2 + (size_t)(m0 + r) * TWP + n0 + c * 8) =
            *reinterpret_cast<const uint4*>(&Cs[r * 136 + c * 8]);
    }
}

// ---------------- messages: block per src, T2 row staged in smem ----------------
__global__ __launch_bounds__(128) void k_msg2() {
    int src = blockIdx.x;
    int s0 = g_off[src], s1 = g_off[src + 1];
    if (s0 == s1) return;
    __shared__ __align__(16) __half tvs[5408];    // T2 row (5402 used)
    __shared__ float rh[8][H];
    __shared__ int tgts[8];
    int tid = threadIdx.x;

    // coalesced stage of the full T2 row: 676 x 16B = 10816B
    {
        const uint4* trow = reinterpret_cast<const uint4*>(g_T2 + (size_t)src * TWP);
        uint4* dst = reinterpret_cast<uint4*>(tvs);
        for (int q = tid; q < 676; q += 128) dst[q] = trow[q];
    }

    for (int base = s0; base < s1; base += 8) {
        int ne = min(8, s1 - base);
        for (int idx = tid; idx < ne * H; idx += 128) {
            int el = idx / H, k = idx - el * H;
            rh[el][k] = g_RH[(size_t)g_eord[base + el] * H + k];
        }
        if (tid < ne) tgts[tid] = g_tgtS[base + tid];
        __syncthreads();
        if (tid < H) {
            const __half* tp = tvs + tid * (H + 1);
            float bterm = __half2float(tp[H]);
            float acc[8];
#pragma unroll
            for (int e = 0; e < 8; e++) acc[e] = bterm;
#pragma unroll 4
            for (int k2 = 0; k2 < 36; k2++) {
                float2 vf = __half22float2(*reinterpret_cast<const __half2*>(tp + 2 * k2));
#pragma unroll
                for (int e = 0; e < 8; e++)
                    if (e < ne) acc[e] += rh[e][2 * k2] * vf.x + rh[e][2 * k2 + 1] * vf.y;
            }
            float v72 = __half2float(tp[72]);
#pragma unroll
            for (int e = 0; e < 8; e++)
                if (e < ne) {
                    acc[e] += rh[e][72] * v72;
                    atomicAdd(&g_agg[(size_t)tgts[e] * H + tid], acc[e]);
                }
        }
        __syncthreads();
    }
}

// ---------------- gates GEMM: C[M,219] = A[M,80] @ B[80,256], fp32 out -----------
template <int AF32>
__global__ __launch_bounds__(256) void k_ggemm(const void* __restrict__ Av,
                                               const __half* __restrict__ B,
                                               float* __restrict__ C) {
    __shared__ __align__(16) __half As[128][88];
    __shared__ __align__(16) __half Bs[80][136];
    int tid = threadIdx.x;
    int m0 = blockIdx.y * 128;
    int n0 = blockIdx.x * 128;

    if (AF32) {
        const float* Af = (const float*)Av;
        for (int idx = tid; idx < 128 * KP; idx += 256) {
            int r = idx / KP, c = idx - r * KP;
            float v = (c < H) ? Af[(size_t)(m0 + r) * H + c] : 0.0f;
            As[r][c] = __float2half(v);
        }
    } else {
        const __half* Ah = (const __half*)Av;
        for (int idx = tid; idx < 1280; idx += 256) {
            int r = idx / 10, c = idx % 10;
            *reinterpret_cast<uint4*>(&As[r][c * 8]) =
                *reinterpret_cast<const uint4*>(Ah + (size_t)(m0 + r) * KP + c * 8);
        }
    }
    for (int idx = tid; idx < 1280; idx += 256) {
        int k = idx >> 4, c = idx & 15;
        *reinterpret_cast<uint4*>(&Bs[k][c * 8]) =
            *reinterpret_cast<const uint4*>(B + (size_t)k * G3P + n0 + c * 8);
    }
    __syncthreads();

    int wid = tid >> 5, lane = tid & 31;
    int wm0 = (wid & 3) * 32;
    int wn0 = (wid >> 2) * 64;

    float acc[2][8][4];
#pragma unroll
    for (int i = 0; i < 2; i++)
#pragma unroll
        for (int j = 0; j < 8; j++)
#pragma unroll
            for (int q = 0; q < 4; q++) acc[i][j][q] = 0.0f;

    unsigned a_base = (unsigned)__cvta_generic_to_shared(&As[0][0]);
    unsigned b_base = (unsigned)__cvta_generic_to_shared(&Bs[0][0]);
    int lr = lane & 15, lc = (lane >> 4) * 8;

#pragma unroll
    for (int ks = 0; ks < 5; ks++) {
        int k0 = ks * 16;
        unsigned af[2][4];
#pragma unroll
        for (int mi = 0; mi < 2; mi++) {
            unsigned addr = a_base + (unsigned)(((wm0 + mi * 16 + lr) * 88 + k0 + lc) * 2);
            ldsm_x4(af[mi][0], af[mi][1], af[mi][2], af[mi][3], addr);
        }
        unsigned bf[4][4];
#pragma unroll
        for (int nj = 0; nj < 4; nj++) {
            unsigned addr = b_base + (unsigned)(((k0 + lr) * 136 + wn0 + nj * 16 + lc) * 2);
            ldsm_x4t(bf[nj][0], bf[nj][1], bf[nj][2], bf[nj][3], addr);
        }
#pragma unroll
        for (int mi = 0; mi < 2; mi++)
#pragma unroll
            for (int nj = 0; nj < 4; nj++) {
                mma16816(acc[mi][2 * nj], af[mi], bf[nj][0], bf[nj][1]);
                mma16816(acc[mi][2 * nj + 1], af[mi], bf[nj][2], bf[nj][3]);
            }
    }

    int gr = lane >> 2, gc = (lane & 3) * 2;
#pragma unroll
    for (int mi = 0; mi < 2; mi++) {
#pragma unroll
        for (int nj8 = 0; nj8 < 8; nj8++) {
            int col = n0 + wn0 + nj8 * 8 + gc;
#pragma unroll
            for (int rr = 0; rr < 2; rr++) {
                int row = m0 + wm0 + mi * 16 + gr + rr * 8;
                if (col + 1 < G3)
                    *reinterpret_cast<float2*>(C + (size_t)row * GLD + col) =
                        make_float2(acc[mi][nj8][rr * 2], acc[mi][nj8][rr * 2 + 1]);
                else if (col < G3)
                    C[(size_t)row * GLD + col] = acc[mi][nj8][rr * 2];
            }
        }
    }
}

// ---------------- GRU pointwise (+ agg re-zero for next step) ----------------
__global__ void k_grupt(const float* __restrict__ bih, const float* __restrict__ bhh) {
    int idx = blockIdx.x * blockDim.x + threadIdx.x;
    if (idx >= N_NODES * KP) return;
    int n = idx / KP, c = idx % KP;
    if (c >= H) { g_h16[idx] = __float2half(0.0f); return; }
    const float* G1 = g_GG1 + (size_t)n * GLD;
    const float* G2 = g_GG2 + (size_t)n * GLD;
    float r = sigf(G1[c] + G2[c] + bih[c] + bhh[c]);
    float z = sigf(G1[H + c] + G2[H + c] + bih[H + c] + bhh[H + c]);
    float nn = tanhf(G1[2 * H + c] + bih[2 * H + c] + r * (G2[2 * H + c] + bhh[2 * H + c]));
    float hv = (1.0f - z) * nn + z * g_h[n * H + c];
    g_h[n * H + c] = hv;
    g_h16[idx] = __float2half(hv);
    g_agg[n * H + c] = 0.0f;
}

// ---------------- Set2Set ----------------
#define EVMAX 2048
__global__ __launch_bounds__(256) void k_s2s(const float* __restrict__ Wih,
                                             const float* __restrict__ Whh,
                                             const float* __restrict__ bih,
                                             const float* __restrict__ bhh,
                                             const float* __restrict__ Wout,
                                             const float* __restrict__ bout,
                                             const int* __restrict__ batch,
                                             float* __restrict__ out) {
    extern __shared__ float sm[];
    float* Wa    = sm;
    float* Wb    = Wa + 292 * 73;
    float* bias  = Wb + 292 * 73;
    float* gates = bias + 292;
    float* hh    = gates + 292;
    float* cc    = hh + 73;
    float* rr    = cc + 73;
    float* rsum  = rr + 73;
    float* ev    = rsum + 73;
    float* red   = ev + EVMAX;

    int tid = threadIdx.x;
    int b = blockIdx.x;

    for (int i = tid; i < 292 * 73; i += 256) {
        int g = i / 73, k = i % 73;
        Wa[i] = Wih[(size_t)g * 146 + k] + Whh[(size_t)g * 73 + k];
        Wb[i] = Wih[(size_t)g * 146 + 73 + k];
    }
    for (int i = tid; i < 292; i += 256) bias[i] = bih[i] + bhh[i];
    if (tid < H) { hh[tid] = 0.0f; cc[tid] = 0.0f; rr[tid] = 0.0f; }

    int lo = 0, hi = N_NODES;
    while (lo < hi) { int mid = (lo + hi) >> 1; if (batch[mid] < b) lo = mid + 1; else hi = mid; }
    int s0 = lo;
    hi = N_NODES;
    while (lo < hi) { int mid = (lo + hi) >> 1; if (batch[mid] < b + 1) lo = mid + 1; else hi = mid; }
    int len = lo - s0;
    if (len > EVMAX) len = EVMAX;
    __syncthreads();

    int lane = tid & 31, w = tid >> 5;

    for (int t = 0; t < T_S2S; t++) {
        for (int g = tid; g < 292; g += 256) {
            const float* wa = Wa + g * 73;
            const float* wb = Wb + g * 73;
            float acc = bias[g];
            for (int k = 0; k < H; k++) acc += hh[k] * wa[k] + rr[k] * wb[k];
            gates[g] = acc;
        }
        __syncthreads();
        if (tid < H) {
            float ig = gates[tid], fg = gates[H + tid], gg = gates[2 * H + tid], og = gates[3 * H + tid];
            float c2 = sigf(fg) * cc[tid] + sigf(ig) * tanhf(gg);
            cc[tid] = c2;
            hh[tid] = sigf(og) * tanhf(c2);
        }
        __syncthreads();

        if (len > 0) {
            for (int n = w; n < len; n += 8) {
                const float* hrow = g_h + (size_t)(s0 + n) * H;
                float acc = 0.0f;
                for (int c = lane; c < H; c += 32) acc += hrow[c] * hh[c];
#pragma unroll
                for (int o = 16; o; o >>= 1) acc += __shfl_down_sync(0xffffffffu, acc, o);
                if (lane == 0) ev[n] = acc;
            }
            __syncthreads();
            float m = -INFINITY;
            for (int n = tid; n < len; n += 256) m = fmaxf(m, ev[n]);
#pragma unroll
            for (int o = 16; o; o >>= 1) m = fmaxf(m, __shfl_xor_sync(0xffffffffu, m, o));
            if (lane == 0) red[w] = m;
            __syncthreads();
            if (tid == 0) {
                float mm = red[0];
                for (int i = 1; i < 8; i++) mm = fmaxf(mm, red[i]);
                red[32] = mm;
            }
            __syncthreads();
            m = red[32];
            float s = 0.0f;
            for (int n = tid; n < len; n += 256) { float a = expf(ev[n] - m); ev[n] = a; s += a; }
#pragma unroll
            for (int o = 16; o; o >>= 1) s += __shfl_xor_sync(0xffffffffu, s, o);
            if (lane == 0) red[w] = s;
            __syncthreads();
            if (tid == 0) {
                float ss = 0.0f;
                for (int i = 0; i < 8; i++) ss += red[i];
                red[33] = ss;
            }
            __syncthreads();
            float inv = 1.0f / red[33];
            if (tid < H) rsum[tid] = 0.0f;
            __syncthreads();
            {
                float a0 = 0.0f, a1 = 0.0f, a2 = 0.0f;
                int c0 = lane, c1 = lane + 32, c2 = lane + 64;
                for (int n = w; n < len; n += 8) {
                    float a = ev[n];
                    const float* hrow = g_h + (size_t)(s0 + n) * H;
                    a0 += a * hrow[c0];
                    a1 += a * hrow[c1];
                    if (lane < 9) a2 += a * hrow[c2];
                }
                atomicAdd(&rsum[c0], a0);
                atomicAdd(&rsum[c1], a1);
                if (lane < 9) atomicAdd(&rsum[c2], a2);
            }
            __syncthreads();
            if (tid < H) rr[tid] = rsum[tid] * inv;
            __syncthreads();
        }
    }

    if (tid == 0) {
        float s = bout[0];
        for (int c = 0; c < H; c++) s += hh[c] * Wout[c];
        out[b] = s;
    }
}

// ---------------- launch ----------------
extern "C" void kernel_launch(void* const* d_in, const int* in_sizes, int n_in,
                              void* d_out, int out_size) {
    const float* nf   = (const float*)d_in[0];
    const float* ef   = (const float*)d_in[1];
    const float* Win  = (const float*)d_in[2];
    const float* bin  = (const float*)d_in[3];
    const float* W1   = (const float*)d_in[4];
    const float* b1   = (const float*)d_in[5];
    const float* W2   = (const float*)d_in[6];
    const float* b2   = (const float*)d_in[7];
    const float* gWih = (const float*)d_in[8];
    const float* gWhh = (const float*)d_in[9];
    const float* gbih = (const float*)d_in[10];
    const float* gbhh = (const float*)d_in[11];
    const float* lWih = (const float*)d_in[12];
    const float* lWhh = (const float*)d_in[13];
    const float* lbih = (const float*)d_in[14];
    const float* lbhh = (const float*)d_in[15];
    const float* Wout = (const float*)d_in[16];
    const float* bout = (const float*)d_in[17];
    const int* Esrc   = (const int*)d_in[18];
    const int* Etgt   = (const int*)d_in[19];
    const int* batch  = (const int*)d_in[20];
    float* out = (float*)d_out;

    __half *p_h16, *p_WihT, *p_WhhT;
    float *p_agg, *p_GG1, *p_GG2;
    cudaGetSymbolAddress((void**)&p_h16, g_h16);
    cudaGetSymbolAddress((void**)&p_WihT, g_WihT);
    cudaGetSymbolAddress((void**)&p_WhhT, g_WhhT);
    cudaGetSymbolAddress((void**)&p_agg, g_agg);
    cudaGetSymbolAddress((void**)&p_GG1, g_GG1);
    cudaGetSymbolAddress((void**)&p_GG2, g_GG2);

    size_t s2s_smem = (size_t)(2 * 292 * 73 + 292 + 292 + 4 * 73 + EVMAX + 34) * sizeof(float);
    cudaFuncSetAttribute(k_s2s, cudaFuncAttributeMaxDynamicSharedMemorySize, (int)s2s_smem);

    dim3 gT(TWP / 128, N_NODES / 128);   // 43 x 64
    dim3 gG(2, N_NODES / 128);           // 2 x 64

    k_prepW2<<<73, 256>>>(W2, b2);                                    // 0
    k_prep<<<NB_H0 + NB_RH, 256>>>(nf, Win, bin, ef, W1, b1);         // 1
    k_scan<<<1, 1024>>>(Esrc);                                         // 2
    k_misc<<<(N_EDGES + 255) / 256, 256>>>(Esrc, Etgt, gWih, gWhh);   // 3

    for (int t = 0; t < T_MP; t++) {
        k_tgemm<<<gT, 256>>>(p_h16);                                   // 4 (t=0)
        k_msg2<<<N_NODES, 128>>>();                                    // 5 (t=0)
        k_ggemm<1><<<gG, 256>>>(p_agg, p_WihT, p_GG1);
        k_ggemm<0><<<gG, 256>>>(p_h16, p_WhhT, p_GG2);
        k_grupt<<<(N_NODES * KP + 255) / 256, 256>>>(gbih, gbhh);
    }

    k_s2s<<<NB, 256, s2s_smem>>>(lWih, lWhh, lbih, lbhh, Wout, bout, batch, out);
}

// round 11
// speedup vs baseline: 1.4019x; 1.0552x over previous
#include <cuda_runtime.h>
#include <cuda_fp16.h>
#include <math.h>

#define N_NODES 8192
#define N_EDGES 32768
#define FN 32
#define FE 16
#define H 73
#define HH (H*H)            // 5329
#define KP 80               // padded K (5 x k16)
#define TW 5402             // T2 logical row width = 73*74
#define TWP 5504            // padded pitch (43*128)
#define GGW 512             // fused GRU weight width (4 x 128)
#define NB 64
#define T_MP 3
#define T_S2S 12

// ---------------- device scratch ----------------
__device__ float g_h[N_NODES * H];
__device__ __half g_h16[N_NODES * KP];
__device__ float g_RH[N_EDGES * H];
__device__ float g_agg[N_NODES * H];
__device__ __half g_T2[(size_t)N_NODES * TWP];    // 90 MB fp16
__device__ __half g_W2e[KP * TWP];
__device__ __half g_Wgru[160 * GGW];              // interleaved block-diag GRU weights
__device__ int g_off[N_NODES + 1];
__device__ int g_cur[N_NODES];
__device__ int g_eord[N_EDGES];
__device__ int g_tgtS[N_EDGES];

__device__ __forceinline__ float sigf(float x) { return 1.0f / (1.0f + expf(-x)); }

__device__ __forceinline__ void ldsm_x4(unsigned &r0, unsigned &r1, unsigned &r2, unsigned &r3, unsigned addr) {
    asm volatile("ldmatrix.sync.aligned.m8n8.x4.shared.b16 {%0,%1,%2,%3},[%4];"
                 : "=r"(r0), "=r"(r1), "=r"(r2), "=r"(r3) : "r"(addr));
}
__device__ __forceinline__ void ldsm_x4t(unsigned &r0, unsigned &r1, unsigned &r2, unsigned &r3, unsigned addr) {
    asm volatile("ldmatrix.sync.aligned.m8n8.x4.trans.shared.b16 {%0,%1,%2,%3},[%4];"
                 : "=r"(r0), "=r"(r1), "=r"(r2), "=r"(r3) : "r"(addr));
}
__device__ __forceinline__ void mma16816(float* d, const unsigned* a, unsigned b0, unsigned b1) {
    asm volatile("mma.sync.aligned.m16n8k16.row.col.f32.f16.f16.f32 "
                 "{%0,%1,%2,%3},{%4,%5,%6,%7},{%8,%9},{%0,%1,%2,%3};"
                 : "+f"(d[0]), "+f"(d[1]), "+f"(d[2]), "+f"(d[3])
                 : "r"(a[0]), "r"(a[1]), "r"(a[2]), "r"(a[3]), "r"(b0), "r"(b1));
}

// ---------------- k_prep: prepW2 (blocks 0..72) + h0 + RH ----------------
#define NB_H0 ((N_NODES * KP) / 256)      // 2560
#define NB_RH ((N_EDGES * H) / 256)       // 9344
__global__ __launch_bounds__(256) void k_prep(const float* __restrict__ nf,
                                              const float* __restrict__ Win,
                                              const float* __restrict__ bin,
                                              const float* __restrict__ ef,
                                              const float* __restrict__ W1,
                                              const float* __restrict__ b1,
                                              const float* __restrict__ W2,
                                              const float* __restrict__ b2) {
    __shared__ float tile[74 * 73];
    int b = blockIdx.x;
    int tid = threadIdx.x;
    if (b < 73) {
        int i = b;
        for (int idx = tid; idx < 74 * 73; idx += 256) {
            int kk = idx / 73, j = idx % 73;
            tile[idx] = (kk < H) ? W2[(size_t)kk * HH + i * H + j] : b2[i * H + j];
        }
        __syncthreads();
        for (int idx = tid; idx < 73 * 74; idx += 256) {
            int j = idx / 74, kk = idx % 74;
            g_W2e[(size_t)j * TWP + i * 74 + kk] = __float2half(tile[kk * 73 + j]);
        }
        const int PAD1 = 7 * TWP, PADT = PAD1 + 73 * 102;
        for (int p = b * 256 + tid; p < PADT; p += 73 * 256) {
            int j, c;
            if (p < PAD1) { j = 73 + p / TWP; c = p % TWP; }
            else { int q = p - PAD1; j = q / 102; c = TW + q % 102; }
            g_W2e[(size_t)j * TWP + c] = __float2half(0.0f);
        }
    } else if (b < 73 + NB_H0) {
        int idx = (b - 73) * 256 + tid;
        if (idx < N_NODES * H) g_agg[idx] = 0.0f;
        int n = idx / KP, c = idx % KP;
        if (c >= H) { g_h16[idx] = __float2half(0.0f); return; }
        const float* x = nf + n * FN;
        float acc = bin[c];
#pragma unroll
        for (int k = 0; k < FN; k++) acc += x[k] * Win[k * H + c];
        g_h[n * H + c] = acc;
        g_h16[idx] = __float2half(acc);
    } else {
        int idx = (b - 73 - NB_H0) * 256 + tid;
        int e = idx / H, c = idx % H;
        const float* x = ef + e * FE;
        float acc = b1[c];
#pragma unroll
        for (int k = 0; k < FE; k++) acc += x[k] * W1[k * H + c];
        g_RH[idx] = fmaxf(acc, 0.0f);
    }
}

// ---------------- scan with in-kernel histogram ----------------
__global__ __launch_bounds__(1024) void k_scan(const int* __restrict__ Esrc) {
    __shared__ int hist[N_NODES];
    __shared__ int sm_[1024];
    int tid = threadIdx.x;
    for (int i = tid; i < N_NODES; i += 1024) hist[i] = 0;
    __syncthreads();
    for (int e = tid; e < N_EDGES; e += 1024) atomicAdd(&hist[Esrc[e]], 1);
    __syncthreads();
    int base = tid * 8;
    int v[8], s = 0;
#pragma unroll
    for (int i = 0; i < 8; i++) { v[i] = hist[base + i]; s += v[i]; }
    sm_[tid] = s;
    __syncthreads();
    for (int off = 1; off < 1024; off <<= 1) {
        int t = (tid >= off) ? sm_[tid - off] : 0;
        __syncthreads();
        sm_[tid] += t;
        __syncthreads();
    }
    int run = sm_[tid] - s;
#pragma unroll
    for (int i = 0; i < 8; i++) {
        g_off[base + i] = run;
        g_cur[base + i] = run;
        run += v[i];
    }
    if (tid == 1023) g_off[N_NODES] = run;
}

// ---------------- misc: scatter edges + interleaved block-diag GRU weights -------
// Column layout: tile t (128 cols) holds channels [21t, 21t+21); channel c uses
// local cols 6*(c-21t)+slot, slot = {0:ir,1:hr,2:iz,3:hz,4:in,5:hn}.
// Rows 0..72 = Wih side (k), rows 80..152 = Whh side (k-80).
__global__ void k_misc(const int* __restrict__ Esrc, const int* __restrict__ Etgt,
                       const float* __restrict__ Wih, const float* __restrict__ Whh) {
    int idx = blockIdx.x * blockDim.x + threadIdx.x;
    if (idx < N_EDGES) {
        int p = atomicAdd(&g_cur[Esrc[idx]], 1);
        g_eord[p] = idx;
        g_tgtS[p] = Etgt[idx];
    }
    if (idx < 160 * GGW) {
        int k = idx >> 9, cc = idx & (GGW - 1);
        int t = cc >> 7, within = cc & 127;
        int j = within / 6, slot = within % 6;
        int c = 21 * t + j;
        float v = 0.0f;
        if (within < 126 && c < H) {
            if (slot == 0 && k < H)            v = Wih[(size_t)c * H + k];
            else if (slot == 2 && k < H)       v = Wih[(size_t)(H + c) * H + k];
            else if (slot == 4 && k < H)       v = Wih[(size_t)(2 * H + c) * H + k];
            else if (slot == 1 && k >= KP && k < KP + H) v = Whh[(size_t)c * H + (k - KP)];
            else if (slot == 3 && k >= KP && k < KP + H) v = Whh[(size_t)(H + c) * H + (k - KP)];
            else if (slot == 5 && k >= KP && k < KP + H) v = Whh[(size_t)(2 * H + c) * H + (k - KP)];
        }
        g_Wgru[idx] = __float2half(v);
    }
}

// ---------------- T2 GEMM: T2[M,TWP] = h16[M,80] @ W2e[80,TWP], fp16 out ----------
__global__ __launch_bounds__(256) void k_tgemm(const __half* __restrict__ A) {
    __shared__ __align__(16) __half sm_u[22144];   // 44288 B
    __half* As = sm_u;                 // [128][88]
    __half* Bs = sm_u + 128 * 88;      // [80][136]
    __half* Cs = sm_u;                 // [128][136] alias
    int tid = threadIdx.x;
    int m0 = blockIdx.y * 128;
    int n0 = blockIdx.x * 128;

    for (int idx = tid; idx < 1280; idx += 256) {
        int r = idx / 10, c = idx % 10;
        *reinterpret_cast<uint4*>(&As[r * 88 + c * 8]) =
            *reinterpret_cast<const uint4*>(A + (size_t)(m0 + r) * KP + c * 8);
    }
    for (int idx = tid; idx < 1280; idx += 256) {
        int k = idx >> 4, c = idx & 15;
        *reinterpret_cast<uint4*>(&Bs[k * 136 + c * 8]) =
            *reinterpret_cast<const uint4*>(g_W2e + (size_t)k * TWP + n0 + c * 8);
    }
    __syncthreads();

    int wid = tid >> 5, lane = tid & 31;
    int wm0 = (wid & 3) * 32;
    int wn0 = (wid >> 2) * 64;

    float acc[2][8][4];
#pragma unroll
    for (int i = 0; i < 2; i++)
#pragma unroll
        for (int j = 0; j < 8; j++)
#pragma unroll
            for (int q = 0; q < 4; q++) acc[i][j][q] = 0.0f;

    unsigned a_base = (unsigned)__cvta_generic_to_shared(As);
    unsigned b_base = (unsigned)__cvta_generic_to_shared(Bs);
    int lr = lane & 15, lc = (lane >> 4) * 8;

#pragma unroll
    for (int ks = 0; ks < 5; ks++) {
        int k0 = ks * 16;
        unsigned af[2][4];
#pragma unroll
        for (int mi = 0; mi < 2; mi++) {
            unsigned addr = a_base + (unsigned)(((wm0 + mi * 16 + lr) * 88 + k0 + lc) * 2);
            ldsm_x4(af[mi][0], af[mi][1], af[mi][2], af[mi][3], addr);
        }
        unsigned bf[4][4];
#pragma unroll
        for (int nj = 0; nj < 4; nj++) {
            unsigned addr = b_base + (unsigned)(((k0 + lr) * 136 + wn0 + nj * 16 + lc) * 2);
            ldsm_x4t(bf[nj][0], bf[nj][1], bf[nj][2], bf[nj][3], addr);
        }
#pragma unroll
        for (int mi = 0; mi < 2; mi++)
#pragma unroll
            for (int nj = 0; nj < 4; nj++) {
                mma16816(acc[mi][2 * nj], af[mi], bf[nj][0], bf[nj][1]);
                mma16816(acc[mi][2 * nj + 1], af[mi], bf[nj][2], bf[nj][3]);
            }
    }
    __syncthreads();

    int gr = lane >> 2, gc = (lane & 3) * 2;
#pragma unroll
    for (int mi = 0; mi < 2; mi++) {
#pragma unroll
        for (int nj8 = 0; nj8 < 8; nj8++) {
            int col = wn0 + nj8 * 8 + gc;
#pragma unroll
            for (int rr = 0; rr < 2; rr++) {
                int row = wm0 + mi * 16 + gr + rr * 8;
                *reinterpret_cast<__half2*>(&Cs[row * 136 + col]) =
                    __floats2half2_rn(acc[mi][nj8][rr * 2], acc[mi][nj8][rr * 2 + 1]);
            }
        }
    }
    __syncthreads();

    for (int idx = tid; idx < 2048; idx += 256) {
        int r = idx >> 4, c = idx & 15;
        *reinterpret_cast<uint4*>(g_T2 + (size_t)(m0 + r) * TWP + n0 + c * 8) =
            *reinterpret_cast<const uint4*>(&Cs[r * 136 + c * 8]);
    }
}

// ---------------- messages: block per src, T2 row staged in smem ----------------
__global__ __launch_bounds__(128) void k_msg2() {
    int src = blockIdx.x;
    int s0 = g_off[src], s1 = g_off[src + 1];
    if (s0 == s1) return;
    __shared__ __align__(16) __half tvs[5408];
    __shared__ float rh[8][H];
    __shared__ int tgts[8];
    int tid = threadIdx.x;

    {
        const uint4* trow = reinterpret_cast<const uint4*>(g_T2 + (size_t)src * TWP);
        uint4* dst = reinterpret_cast<uint4*>(tvs);
        for (int q = tid; q < 676; q += 128) dst[q] = trow[q];
    }

    for (int base = s0; base < s1; base += 8) {
        int ne = min(8, s1 - base);
        for (int idx = tid; idx < ne * H; idx += 128) {
            int el = idx / H, k = idx - el * H;
            rh[el][k] = g_RH[(size_t)g_eord[base + el] * H + k];
        }
        if (tid < ne) tgts[tid] = g_tgtS[base + tid];
        __syncthreads();
        if (tid < H) {
            const __half* tp = tvs + tid * (H + 1);
            float bterm = __half2float(tp[H]);
            float acc[8];
#pragma unroll
            for (int e = 0; e < 8; e++) acc[e] = bterm;
#pragma unroll 4
            for (int k2 = 0; k2 < 36; k2++) {
                float2 vf = __half22float2(*reinterpret_cast<const __half2*>(tp + 2 * k2));
#pragma unroll
                for (int e = 0; e < 8; e++)
                    if (e < ne) acc[e] += rh[e][2 * k2] * vf.x + rh[e][2 * k2 + 1] * vf.y;
            }
            float v72 = __half2float(tp[72]);
#pragma unroll
            for (int e = 0; e < 8; e++)
                if (e < ne) {
                    acc[e] += rh[e][72] * v72;
                    atomicAdd(&g_agg[(size_t)tgts[e] * H + tid], acc[e]);
                }
        }
        __syncthreads();
    }
}

// ---------------- fused GRU: gates GEMM (K=160) + pointwise epilogue --------------
// grid (4, 64). Block (nt, mb): rows mb*128..+128, channels 21*nt..+{21|10}.
// A = [agg fp16 | h16] (built in smem), B = g_Wgru tile. C staged fp32 in smem.
__global__ __launch_bounds__(256) void k_gruf(const float* __restrict__ bih,
                                              const float* __restrict__ bhh) {
    extern __shared__ __half sh[];
    __half* As = sh;                  // [128][168]  (43008 B)
    __half* Bs = sh + 128 * 168;      // [160][136]  (43520 B)
    float* Cs = reinterpret_cast<float*>(sh);   // [128][132] alias (67584 B)
    int tid = threadIdx.x;
    int nt = blockIdx.x;
    int m0 = blockIdx.y * 128;
    int n0 = nt * 128;

    // A: cols 0..79 = agg (fp32->fp16), cols 80..159 = h16
    for (int idx = tid; idx < 128 * KP; idx += 256) {
        int r = idx / KP, c = idx - r * KP;
        As[r * 168 + c] = __float2half((c < H) ? g_agg[(size_t)(m0 + r) * H + c] : 0.0f);
    }
    for (int idx = tid; idx < 128 * 10; idx += 256) {
        int r = idx / 10, q = idx - r * 10;
        *reinterpret_cast<uint4*>(&As[r * 168 + KP + q * 8]) =
            *reinterpret_cast<const uint4*>(g_h16 + (size_t)(m0 + r) * KP + q * 8);
    }
    for (int idx = tid; idx < 160 * 16; idx += 256) {
        int k = idx >> 4, c = idx & 15;
        *reinterpret_cast<uint4*>(&Bs[k * 136 + c * 8]) =
            *reinterpret_cast<const uint4*>(g_Wgru + (size_t)k * GGW + n0 + c * 8);
    }
    __syncthreads();

    int wid = tid >> 5, lane = tid & 31;
    int wm0 = (wid & 3) * 32;
    int wn0 = (wid >> 2) * 64;

    float acc[2][8][4];
#pragma unroll
    for (int i = 0; i < 2; i++)
#pragma unroll
        for (int j = 0; j < 8; j++)
#pragma unroll
            for (int q = 0; q < 4; q++) acc[i][j][q] = 0.0f;

    unsigned a_base = (unsigned)__cvta_generic_to_shared(As);
    unsigned b_base = (unsigned)__cvta_generic_to_shared(Bs);
    int lr = lane & 15, lc = (lane >> 4) * 8;

#pragma unroll
    for (int ks = 0; ks < 10; ks++) {
        int k0 = ks * 16;
        unsigned af[2][4];
#pragma unroll
        for (int mi = 0; mi < 2; mi++) {
            unsigned addr = a_base + (unsigned)(((wm0 + mi * 16 + lr) * 168 + k0 + lc) * 2);
            ldsm_x4(af[mi][0], af[mi][1], af[mi][2], af[mi][3], addr);
        }
        unsigned bf[4][4];
#pragma unroll
        for (int nj = 0; nj < 4; nj++) {
            unsigned addr = b_base + (unsigned)(((k0 + lr) * 136 + wn0 + nj * 16 + lc) * 2);
            ldsm_x4t(bf[nj][0], bf[nj][1], bf[nj][2], bf[nj][3], addr);
        }
#pragma unroll
        for (int mi = 0; mi < 2; mi++)
#pragma unroll
            for (int nj = 0; nj < 4; nj++) {
                mma16816(acc[mi][2 * nj], af[mi], bf[nj][0], bf[nj][1]);
                mma16816(acc[mi][2 * nj + 1], af[mi], bf[nj][2], bf[nj][3]);
            }
    }
    __syncthreads();   // smem reads done; alias as fp32 C tile

    int gr = lane >> 2, gc = (lane & 3) * 2;
#pragma unroll
    for (int mi = 0; mi < 2; mi++) {
#pragma unroll
        for (int nj8 = 0; nj8 < 8; nj8++) {
            int col = wn0 + nj8 * 8 + gc;
#pragma unroll
            for (int rr = 0; rr < 2; rr++) {
                int row = wm0 + mi * 16 + gr + rr * 8;
                *reinterpret_cast<float2*>(&Cs[row * 132 + col]) =
                    make_float2(acc[mi][nj8][rr * 2], acc[mi][nj8][rr * 2 + 1]);
            }
        }
    }
    __syncthreads();

    // pointwise GRU for channels of this tile
    int ch0 = 21 * nt;
    int nch = min(21, H - ch0);
    for (int idx = tid; idx < 128 * nch; idx += 256) {
        int r = idx / nch, j = idx - r * nch;
        int c = ch0 + j;
        const float* gbase = &Cs[r * 132 + 6 * j];
        float ir = gbase[0], hr = gbase[1], iz = gbase[2];
        float hz = gbase[3], inn = gbase[4], hn = gbase[5];
        float rg = sigf(ir + hr + bih[c] + bhh[c]);
        float z  = sigf(iz + hz + bih[H + c] + bhh[H + c]);
        float nn = tanhf(inn + bih[2 * H + c] + rg * (hn + bhh[2 * H + c]));
        size_t n = (size_t)(m0 + r);
        float hv = (1.0f - z) * nn + z * g_h[n * H + c];
        g_h[n * H + c] = hv;
        g_h16[n * KP + c] = __float2half(hv);
        g_agg[n * H + c] = 0.0f;
    }
}

// ---------------- Set2Set ----------------
#define EVMAX 2048
__global__ __launch_bounds__(256) void k_s2s(const float* __restrict__ Wih,
                                             const float* __restrict__ Whh,
                                             const float* __restrict__ bih,
                                             const float* __restrict__ bhh,
                                             const float* __restrict__ Wout,
                                             const float* __restrict__ bout,
                                             const int* __restrict__ batch,
                                             float* __restrict__ out) {
    extern __shared__ float sm[];
    float* Wa    = sm;
    float* Wb    = Wa + 292 * 73;
    float* bias  = Wb + 292 * 73;
    float* gates = bias + 292;
    float* hh    = gates + 292;
    float* cc    = hh + 73;
    float* rr    = cc + 73;
    float* rsum  = rr + 73;
    float* ev    = rsum + 73;
    float* red   = ev + EVMAX;

    int tid = threadIdx.x;
    int b = blockIdx.x;

    for (int i = tid; i < 292 * 73; i += 256) {
        int g = i / 73, k = i % 73;
        Wa[i] = Wih[(size_t)g * 146 + k] + Whh[(size_t)g * 73 + k];
        Wb[i] = Wih[(size_t)g * 146 + 73 + k];
    }
    for (int i = tid; i < 292; i += 256) bias[i] = bih[i] + bhh[i];
    if (tid < H) { hh[tid] = 0.0f; cc[tid] = 0.0f; rr[tid] = 0.0f; }

    int lo = 0, hi = N_NODES;
    while (lo < hi) { int mid = (lo + hi) >> 1; if (batch[mid] < b) lo = mid + 1; else hi = mid; }
    int s0 = lo;
    hi = N_NODES;
    while (lo < hi) { int mid = (lo + hi) >> 1; if (batch[mid] < b + 1) lo = mid + 1; else hi = mid; }
    int len = lo - s0;
    if (len > EVMAX) len = EVMAX;
    __syncthreads();

    int lane = tid & 31, w = tid >> 5;

    for (int t = 0; t < T_S2S; t++) {
        for (int g = tid; g < 292; g += 256) {
            const float* wa = Wa + g * 73;
            const float* wb = Wb + g * 73;
            float acc = bias[g];
            for (int k = 0; k < H; k++) acc += hh[k] * wa[k] + rr[k] * wb[k];
            gates[g] = acc;
        }
        __syncthreads();
        if (tid < H) {
            float ig = gates[tid], fg = gates[H + tid], gg = gates[2 * H + tid], og = gates[3 * H + tid];
            float c2 = sigf(fg) * cc[tid] + sigf(ig) * tanhf(gg);
            cc[tid] = c2;
            hh[tid] = sigf(og) * tanhf(c2);
        }
        __syncthreads();

        if (len > 0) {
            for (int n = w; n < len; n += 8) {
                const float* hrow = g_h + (size_t)(s0 + n) * H;
                float acc = 0.0f;
                for (int c = lane; c < H; c += 32) acc += hrow[c] * hh[c];
#pragma unroll
                for (int o = 16; o; o >>= 1) acc += __shfl_down_sync(0xffffffffu, acc, o);
                if (lane == 0) ev[n] = acc;
            }
            __syncthreads();
            float m = -INFINITY;
            for (int n = tid; n < len; n += 256) m = fmaxf(m, ev[n]);
#pragma unroll
            for (int o = 16; o; o >>= 1) m = fmaxf(m, __shfl_xor_sync(0xffffffffu, m, o));
            if (lane == 0) red[w] = m;
            __syncthreads();
            if (tid == 0) {
                float mm = red[0];
                for (int i = 1; i < 8; i++) mm = fmaxf(mm, red[i]);
                red[32] = mm;
            }
            __syncthreads();
            m = red[32];
            float s = 0.0f;
            for (int n = tid; n < len; n += 256) { float a = expf(ev[n] - m); ev[n] = a; s += a; }
#pragma unroll
            for (int o = 16; o; o >>= 1) s += __shfl_xor_sync(0xffffffffu, s, o);
            if (lane == 0) red[w] = s;
            __syncthreads();
            if (tid == 0) {
                float ss = 0.0f;
                for (int i = 0; i < 8; i++) ss += red[i];
                red[33] = ss;
            }
            __syncthreads();
            float inv = 1.0f / red[33];
            if (tid < H) rsum[tid] = 0.0f;
            __syncthreads();
            {
                float a0 = 0.0f, a1 = 0.0f, a2 = 0.0f;
                int c0 = lane, c1 = lane + 32, c2 = lane + 64;
                for (int n = w; n < len; n += 8) {
                    float a = ev[n];
                    const float* hrow = g_h + (size_t)(s0 + n) * H;
                    a0 += a * hrow[c0];
                    a1 += a * hrow[c1];
                    if (lane < 9) a2 += a * hrow[c2];
                }
                atomicAdd(&rsum[c0], a0);
                atomicAdd(&rsum[c1], a1);
                if (lane < 9) atomicAdd(&rsum[c2], a2);
            }
            __syncthreads();
            if (tid < H) rr[tid] = rsum[tid] * inv;
            __syncthreads();
        }
    }

    if (tid == 0) {
        float s = bout[0];
        for (int c = 0; c < H; c++) s += hh[c] * Wout[c];
        out[b] = s;
    }
}

// ---------------- launch ----------------
extern "C" void kernel_launch(void* const* d_in, const int* in_sizes, int n_in,
                              void* d_out, int out_size) {
    const float* nf   = (const float*)d_in[0];
    const float* ef   = (const float*)d_in[1];
    const float* Win  = (const float*)d_in[2];
    const float* bin  = (const float*)d_in[3];
    const float* W1   = (const float*)d_in[4];
    const float* b1   = (const float*)d_in[5];
    const float* W2   = (const float*)d_in[6];
    const float* b2   = (const float*)d_in[7];
    const float* gWih = (const float*)d_in[8];
    const float* gWhh = (const float*)d_in[9];
    const float* gbih = (const float*)d_in[10];
    const float* gbhh = (const float*)d_in[11];
    const float* lWih = (const float*)d_in[12];
    const float* lWhh = (const float*)d_in[13];
    const float* lbih = (const float*)d_in[14];
    const float* lbhh = (const float*)d_in[15];
    const float* Wout = (const float*)d_in[16];
    const float* bout = (const float*)d_in[17];
    const int* Esrc   = (const int*)d_in[18];
    const int* Etgt   = (const int*)d_in[19];
    const int* batch  = (const int*)d_in[20];
    float* out = (float*)d_out;

    __half *p_h16;
    cudaGetSymbolAddress((void**)&p_h16, g_h16);

    const int SMG = (128 * 168 + 160 * 136) * 2;   // 86528
    cudaFuncSetAttribute(k_gruf, cudaFuncAttributeMaxDynamicSharedMemorySize, SMG);
    size_t s2s_smem = (size_t)(2 * 292 * 73 + 292 + 292 + 4 * 73 + EVMAX + 34) * sizeof(float);
    cudaFuncSetAttribute(k_s2s, cudaFuncAttributeMaxDynamicSharedMemorySize, (int)s2s_smem);

    dim3 gT(TWP / 128, N_NODES / 128);   // 43 x 64
    dim3 gG(4, N_NODES / 128);           // 4 x 64

    k_prep<<<73 + NB_H0 + NB_RH, 256>>>(nf, Win, bin, ef, W1, b1, W2, b2);  // 0
    k_scan<<<1, 1024>>>(Esrc);                                               // 1
    k_misc<<<(160 * GGW + 255) / 256, 256>>>(Esrc, Etgt, gWih, gWhh);       // 2

    for (int t = 0; t < T_MP; t++) {
        k_tgemm<<<gT, 256>>>(p_h16);
        k_msg2<<<N_NODES, 128>>>();
        k_gruf<<<gG, 256, SMG>>>(gbih, gbhh);
    }

    k_s2s<<<NB, 256, s2s_smem>>>(lWih, lWhh, lbih, lbhh, Wout, bout, batch, out);
}